// round 4
// baseline (speedup 1.0000x reference)
#include <cuda_runtime.h>
#include <math.h>

// Problem constants (fixed by setup_inputs)
#define BS   16
#define NQ   550
#define NC   91
#define NT   48
#define GN   11      // group_num
#define GQ   (NQ / GN)       // 50 queries per group
#define NTOT (BS * NT)       // 768 total targets (cost matrix cols)
#define NMATCH (GN * NT)     // 528 matches per batch

#define LSA_N 48   // rows of transposed problem (targets)
#define LSA_M 50   // cols of transposed problem (queries)

// ---------------------------------------------------------------------------
// Kernel 1: cost matrix  C[b, q, t_global]  (bs*nq x bs*nt)
// ---------------------------------------------------------------------------
__global__ void cost_kernel(const float* __restrict__ logits,   // (BS*NQ, NC)
                            const float* __restrict__ pboxes,   // (BS*NQ, 6)
                            const int*   __restrict__ labels,   // (NTOT)
                            const float* __restrict__ tboxes,   // (NTOT, 6)
                            float* __restrict__ C)               // (BS*NQ, NTOT)
{
    int idx = blockIdx.x * blockDim.x + threadIdx.x;
    const int TOT = BS * NQ * NTOT;
    if (idx >= TOT) return;
    int q = idx / NTOT;
    int t = idx - q * NTOT;

    const float* qb = pboxes + q * 6;
    float cx = qb[0], cy = qb[1], l = qb[2], r = qb[3], tp = qb[4], bo = qb[5];
    const float* tb = tboxes + t * 6;
    float tcx = tb[0], tcy = tb[1], tl = tb[2], tr = tb[3], ttp = tb[4], tbo = tb[5];

    // focal cost_class
    int cls = labels[t];
    float x = logits[q * NC + cls];
    float p = 1.0f / (1.0f + expf(-x));
    float omp = 1.0f - p;
    float pos = 0.25f * omp * omp * (-logf(p + 1e-8f));
    float neg = 0.75f * p * p * (-logf(omp + 1e-8f));
    float cost_class = pos - neg;

    // L1 costs
    float c3d   = fabsf(cx - tcx) + fabsf(cy - tcy);
    float cbbox = fabsf(l - tl) + fabsf(r - tr) + fabsf(tp - ttp) + fabsf(bo - tbo);

    // GIoU (cxcylrtb -> xyxy)
    float ax0 = cx - l,   ay0 = cy - tp,  ax1 = cx + r,   ay1 = cy + bo;
    float bx0 = tcx - tl, by0 = tcy - ttp, bx1 = tcx + tr, by1 = tcy + tbo;
    float a1 = (ax1 - ax0) * (ay1 - ay0);
    float a2 = (bx1 - bx0) * (by1 - by0);
    float iw = fmaxf(fminf(ax1, bx1) - fmaxf(ax0, bx0), 0.0f);
    float ih = fmaxf(fminf(ay1, by1) - fmaxf(ay0, by0), 0.0f);
    float inter = iw * ih;
    float uni = a1 + a2 - inter;
    float iou = inter / uni;
    float ew = fmaxf(fmaxf(ax1, bx1) - fminf(ax0, bx0), 0.0f);
    float eh = fmaxf(fmaxf(ay1, by1) - fminf(ay0, by0), 0.0f);
    float ae = ew * eh;
    float giou = iou - (ae - uni) / ae;

    C[idx] = 5.0f * cbbox + 10.0f * c3d + 2.0f * cost_class + 2.0f * (-giou);
}

// ---------------------------------------------------------------------------
// Kernel 2: Jonker-Volgenant LSA, one warp per (batch, group) problem.
// Works on the TRANSPOSED 48x50 block (n=48 targets rows, m=50 query cols),
// exactly mirroring the numpy reference (float64 arithmetic).
// ---------------------------------------------------------------------------
__global__ void lsa_kernel(const float* __restrict__ C,
                           float* __restrict__ pi_out,   // (BS, NMATCH)
                           float* __restrict__ ti_out)   // (BS, NMATCH)
{
    int prob = blockIdx.x;            // 0..175
    int b = prob / GN;
    int g = prob - b * GN;
    int lane = threadIdx.x;           // 32 threads

    __shared__ double cost[LSA_N][LSA_M];
    __shared__ double u[LSA_N + 1];
    __shared__ double v[LSA_M + 1];
    __shared__ double minv[LSA_M + 1];
    __shared__ int p[LSA_M + 1];
    __shared__ int way[LSA_M + 1];
    __shared__ int used[LSA_M + 1];

    // Load transposed cost block: cost[i][j] = C[b, g*GQ + j, b*NT + i]
    for (int idx = lane; idx < LSA_N * LSA_M; idx += 32) {
        int i = idx / LSA_M;
        int j = idx - i * LSA_M;
        size_t off = ((size_t)(b * NQ + g * GQ + j)) * NTOT + (size_t)(b * NT + i);
        cost[i][j] = (double)C[off];
    }
    for (int j = lane; j <= LSA_M; j += 32) { v[j] = 0.0; p[j] = 0; way[j] = 0; }
    for (int i = lane; i <= LSA_N; i += 32) u[i] = 0.0;
    __syncwarp();

    for (int i = 1; i <= LSA_N; i++) {
        if (lane == 0) p[0] = i;
        for (int j = lane; j <= LSA_M; j += 32) { minv[j] = INFINITY; used[j] = 0; }
        __syncwarp();

        int j0 = 0;
        while (true) {
            if (lane == 0) used[j0] = 1;
            __syncwarp();
            int i0 = p[j0];
            double ui0 = u[i0];

            // relax free columns
            for (int j = lane + 1; j <= LSA_M; j += 32) {
                if (!used[j]) {
                    double cur = cost[i0 - 1][j - 1] - ui0 - v[j];
                    if (cur < minv[j]) { minv[j] = cur; way[j] = j0; }
                }
            }
            __syncwarp();

            // argmin over free columns, ties -> smallest j (matches np.argmin)
            double bestv = INFINITY;
            int bestj = LSA_M + 1;
            for (int j = lane + 1; j <= LSA_M; j += 32) {
                if (!used[j] && minv[j] < bestv) { bestv = minv[j]; bestj = j; }
            }
            #pragma unroll
            for (int off = 16; off > 0; off >>= 1) {
                double ov = __shfl_down_sync(0xffffffff, bestv, off);
                int    oj = __shfl_down_sync(0xffffffff, bestj, off);
                if (ov < bestv || (ov == bestv && oj < bestj)) { bestv = ov; bestj = oj; }
            }
            bestv = __shfl_sync(0xffffffff, bestv, 0);
            bestj = __shfl_sync(0xffffffff, bestj, 0);
            double delta = bestv;

            // dual updates (p[j] values distinct over used j -> no conflicts)
            for (int j = lane; j <= LSA_M; j += 32) {
                if (used[j]) { u[p[j]] += delta; v[j] -= delta; }
                else         { minv[j] -= delta; }
            }
            __syncwarp();

            j0 = bestj;
            if (p[j0] == 0) break;
        }

        // augment along alternating path (serial, tiny)
        if (lane == 0) {
            int jc = j0;
            while (jc) { int jn = way[jc]; p[jc] = p[jn]; jc = jn; }
        }
        __syncwarp();
    }

    // Emit matches: queries ascending (exactly 48 of 50 columns assigned)
    if (lane == 0) {
        int base = b * NMATCH + g * NT;
        int k = 0;
        for (int j = 1; j <= LSA_M; j++) {
            if (p[j]) {
                pi_out[base + k] = (float)(g * GQ + j - 1);  // query index
                ti_out[base + k] = (float)(p[j] - 1);        // target index
                k++;
            }
        }
    }
}

// ---------------------------------------------------------------------------
extern "C" void kernel_launch(void* const* d_in, const int* in_sizes, int n_in,
                              void* d_out, int out_size)
{
    const float* logits = (const float*)d_in[0];  // (16,550,91)
    const float* pboxes = (const float*)d_in[1];  // (16,550,6)
    const int*   labels = (const int*)  d_in[2];  // (16,48)
    const float* tboxes = (const float*)d_in[3];  // (16,48,6)

    float* C  = (float*)d_out;
    const int C_ELEMS = BS * NQ * NTOT;          // 6,758,400
    float* pi = C + C_ELEMS;
    float* ti = pi + BS * NMATCH;

    int tot = C_ELEMS;
    cost_kernel<<<(tot + 255) / 256, 256>>>(logits, pboxes, labels, tboxes, C);

    if (out_size >= C_ELEMS + 2 * BS * NMATCH) {
        lsa_kernel<<<BS * GN, 32>>>(C, pi, ti);
    }
}

// round 5
// speedup vs baseline: 1.7968x; 1.7968x over previous
#include <cuda_runtime.h>
#include <math.h>

// Problem constants (fixed by setup_inputs)
#define BS   16
#define NQ   550
#define NC   91
#define NT   48
#define GN   11
#define GQ   (NQ / GN)       // 50
#define NTOT (BS * NT)       // 768
#define NMATCH (GN * NT)     // 528

#define LSA_N 48   // rows (targets) of transposed problem
#define LSA_M 50   // cols (queries)

// scratch: focal class cost per (q, class)
__device__ float g_focal[BS * NQ * NC];

// ---------------------------------------------------------------------------
// Kernel 0: focal class cost per (query, class)  — 800k elems
// ---------------------------------------------------------------------------
__global__ void focal_kernel(const float* __restrict__ logits)
{
    int idx = blockIdx.x * blockDim.x + threadIdx.x;
    if (idx >= BS * NQ * NC) return;
    float x = logits[idx];
    float p = 1.0f / (1.0f + expf(-x));
    float omp = 1.0f - p;
    float pos = 0.25f * omp * omp * (-logf(p + 1e-8f));
    float neg = 0.75f * p * p * (-logf(omp + 1e-8f));
    g_focal[idx] = pos - neg;
}

// ---------------------------------------------------------------------------
// Kernel 1: cost matrix  C[b, q, t_global]
// ---------------------------------------------------------------------------
__global__ void cost_kernel(const float* __restrict__ pboxes,   // (BS*NQ, 6)
                            const int*   __restrict__ labels,   // (NTOT)
                            const float* __restrict__ tboxes,   // (NTOT, 6)
                            float* __restrict__ C)               // (BS*NQ, NTOT)
{
    int idx = blockIdx.x * blockDim.x + threadIdx.x;
    const int TOT = BS * NQ * NTOT;
    if (idx >= TOT) return;
    int q = idx / NTOT;
    int t = idx - q * NTOT;

    const float* qb = pboxes + q * 6;
    float cx = qb[0], cy = qb[1], l = qb[2], r = qb[3], tp = qb[4], bo = qb[5];
    const float* tb = tboxes + t * 6;
    float tcx = tb[0], tcy = tb[1], tl = tb[2], tr = tb[3], ttp = tb[4], tbo = tb[5];

    float cost_class = g_focal[q * NC + labels[t]];

    float c3d   = fabsf(cx - tcx) + fabsf(cy - tcy);
    float cbbox = fabsf(l - tl) + fabsf(r - tr) + fabsf(tp - ttp) + fabsf(bo - tbo);

    float ax0 = cx - l,   ay0 = cy - tp,   ax1 = cx + r,   ay1 = cy + bo;
    float bx0 = tcx - tl, by0 = tcy - ttp, bx1 = tcx + tr, by1 = tcy + tbo;
    float a1 = (ax1 - ax0) * (ay1 - ay0);
    float a2 = (bx1 - bx0) * (by1 - by0);
    float iw = fmaxf(fminf(ax1, bx1) - fmaxf(ax0, bx0), 0.0f);
    float ih = fmaxf(fminf(ay1, by1) - fmaxf(ay0, by0), 0.0f);
    float inter = iw * ih;
    float uni = a1 + a2 - inter;
    float iou = inter / uni;
    float ew = fmaxf(fmaxf(ax1, bx1) - fminf(ax0, bx0), 0.0f);
    float eh = fmaxf(fmaxf(ay1, by1) - fminf(ay0, by0), 0.0f);
    float ae = ew * eh;
    float giou = iou - (ae - uni) / ae;

    C[idx] = 5.0f * cbbox + 10.0f * c3d + 2.0f * cost_class + 2.0f * (-giou);
}

// ---------------------------------------------------------------------------
// monotone f64 <-> uint64 key (order-preserving), for integer argmin
// ---------------------------------------------------------------------------
__device__ __forceinline__ unsigned long long dkey(double d) {
    long long ll = __double_as_longlong(d);
    return (unsigned long long)(ll ^ ((ll >> 63) | 0x8000000000000000LL));
}
__device__ __forceinline__ double dunkey(unsigned long long k) {
    long long kl = (long long)k;
    kl ^= (((~kl) >> 63) | 0x8000000000000000LL);
    return __longlong_as_double(kl);
}

// ---------------------------------------------------------------------------
// Kernel 2: Jonker-Volgenant LSA, one warp per (batch, group) problem.
// Transposed 48x50 block, f64 dual arithmetic bit-matching the numpy
// reference; per-column state in registers (2 cols/lane), argmin via
// integer-key butterfly.
// ---------------------------------------------------------------------------
__global__ void __launch_bounds__(32, 8)
lsa_kernel(const float* __restrict__ C,
           float* __restrict__ pi_out,   // (BS, NMATCH)
           float* __restrict__ ti_out)   // (BS, NMATCH)
{
    int prob = blockIdx.x;            // 0..175
    int b = prob / GN;
    int g = prob - b * GN;
    int lane = threadIdx.x;

    __shared__ float costp[LSA_N][64];      // [row i][col j], lane's cols adjacent
    __shared__ double u_s[LSA_N + 1];
    __shared__ int p_s[LSA_M + 1];
    __shared__ int way_s[LSA_M + 1];

    // Load cost block (coalesced over targets i): cost[i][j] = C[b, g*GQ+j, b*NT+i]
    for (int idx = lane; idx < LSA_N * LSA_M; idx += 32) {
        int j = idx / LSA_N;
        int i = idx - j * LSA_N;
        costp[i][j] = C[(size_t)(b * NQ + g * GQ + j) * NTOT + (size_t)(b * NT + i)];
    }
    for (int x = lane; x <= LSA_N; x += 32) u_s[x] = 0.0;
    for (int x = lane; x <= LSA_M; x += 32) { p_s[x] = 0; way_s[x] = 0; }
    __syncwarp();

    const bool act = (lane < 25);
    const int colA = 2 * lane + 1;          // 1-based column ids owned by lane
    const int colB = 2 * lane + 2;
    double v0 = 0.0, v1 = 0.0;              // dual v for my cols
    int pr0 = 0, pr1 = 0;                   // register mirror of p_s for my cols

    for (int i = 1; i <= LSA_N; i++) {
        double m0 = INFINITY, m1 = INFINITY;    // minv for my cols
        unsigned used2 = act ? 0u : 3u;
        int j0 = 0;

        while (true) {
            // mark j0 used (owner lane)
            if (j0 > 0 && lane == ((j0 - 1) >> 1)) used2 |= 1u << ((j0 - 1) & 1);

            int i0 = (j0 == 0) ? i : p_s[j0];
            double ui0 = u_s[i0];
            float2 cf = *(const float2*)&costp[i0 - 1][2 * lane];

            if (act) {
                if (!(used2 & 1u)) {
                    double cur = ((double)cf.x - ui0) - v0;
                    if (cur < m0) { m0 = cur; way_s[colA] = j0; }
                }
                if (!(used2 & 2u)) {
                    double cur = ((double)cf.y - ui0) - v1;
                    if (cur < m1) { m1 = cur; way_s[colB] = j0; }
                }
            }

            // lane-local best, then warp butterfly on (uint64 key, col)
            unsigned long long k0 = (used2 & 1u) ? ~0ULL : dkey(m0);
            unsigned long long k1 = (used2 & 2u) ? ~0ULL : dkey(m1);
            unsigned long long bk; int bj;
            if (k0 <= k1) { bk = k0; bj = colA; } else { bk = k1; bj = colB; }
            #pragma unroll
            for (int off = 16; off; off >>= 1) {
                unsigned long long ok = __shfl_xor_sync(0xffffffffu, bk, off);
                int                oj = __shfl_xor_sync(0xffffffffu, bj, off);
                if (ok < bk || (ok == bk && oj < bj)) { bk = ok; bj = oj; }
            }
            double delta = dunkey(bk);

            // dual updates: u[p[used]] += delta; v[used] -= delta; minv[free] -= delta
            if (act) {
                if (used2 & 1u) { v0 -= delta; u_s[pr0] += delta; } else { m0 -= delta; }
                if (used2 & 2u) { v1 -= delta; u_s[pr1] += delta; } else { m1 -= delta; }
            }
            if (lane == 31) u_s[i] += delta;      // p[0] = i
            __syncwarp();

            j0 = bj;
            if (p_s[j0] == 0) break;
        }

        // augment alternating path (serial, short)
        if (lane == 0) {
            int jc = j0;
            while (jc) {
                int jn = way_s[jc];
                p_s[jc] = (jn == 0) ? i : p_s[jn];
                jc = jn;
            }
        }
        __syncwarp();
        if (act) { pr0 = p_s[colA]; pr1 = p_s[colB]; }
        __syncwarp();
    }

    // Emit matches: queries ascending (48 of 50 columns assigned)
    if (lane == 0) {
        int base = b * NMATCH + g * NT;
        int k = 0;
        for (int j = 1; j <= LSA_M; j++) {
            int pj = p_s[j];
            if (pj) {
                pi_out[base + k] = (float)(g * GQ + j - 1);
                ti_out[base + k] = (float)(pj - 1);
                k++;
            }
        }
    }
}

// ---------------------------------------------------------------------------
extern "C" void kernel_launch(void* const* d_in, const int* in_sizes, int n_in,
                              void* d_out, int out_size)
{
    const float* logits = (const float*)d_in[0];  // (16,550,91)
    const float* pboxes = (const float*)d_in[1];  // (16,550,6)
    const int*   labels = (const int*)  d_in[2];  // (16,48)
    const float* tboxes = (const float*)d_in[3];  // (16,48,6)

    float* C  = (float*)d_out;
    const int C_ELEMS = BS * NQ * NTOT;          // 6,758,400
    float* pi = C + C_ELEMS;
    float* ti = pi + BS * NMATCH;

    int nfoc = BS * NQ * NC;
    focal_kernel<<<(nfoc + 255) / 256, 256>>>(logits);

    int tot = C_ELEMS;
    cost_kernel<<<(tot + 255) / 256, 256>>>(pboxes, labels, tboxes, C);

    if (out_size >= C_ELEMS + 2 * BS * NMATCH) {
        lsa_kernel<<<BS * GN, 32>>>(C, pi, ti);
    }
}

// round 7
// speedup vs baseline: 2.4997x; 1.3912x over previous
#include <cuda_runtime.h>
#include <math.h>

// Problem constants (fixed by setup_inputs)
#define BS   16
#define NQ   550
#define NC   91
#define NT   48
#define GN   11
#define GQ   (NQ / GN)       // 50
#define NTOT (BS * NT)       // 768
#define NMATCH (GN * NT)     // 528

#define LSA_N 48   // rows (targets) of transposed problem
#define LSA_M 50   // cols (queries)
#define NPROB (BS * GN)      // 176 LSA problems
#define COST_BLOCKS 6600     // 6,758,400 / (256*4)
#define FULLMASK 0xffffffffu

// scratch: focal class cost per (q, class)
__device__ float g_focal[BS * NQ * NC];

// ---------------------------------------------------------------------------
// Kernel 0: focal class cost per (query, class)  — 800k elems
// ---------------------------------------------------------------------------
__global__ void focal_kernel(const float* __restrict__ logits)
{
    int idx = blockIdx.x * blockDim.x + threadIdx.x;
    if (idx >= BS * NQ * NC) return;
    float x = logits[idx];
    float p = 1.0f / (1.0f + expf(-x));
    float omp = 1.0f - p;
    float pos = 0.25f * omp * omp * (-logf(p + 1e-8f));
    float neg = 0.75f * p * p * (-logf(omp + 1e-8f));
    g_focal[idx] = pos - neg;
}

// ---------------------------------------------------------------------------
// Shared cost evaluation (identical expression everywhere)
// ---------------------------------------------------------------------------
__device__ __forceinline__ float cost_eval(
    float cx, float cy, float l, float r, float tp, float bo,   // query box
    int q, int t,
    const int* __restrict__ labels, const float* __restrict__ tboxes)
{
    const float* tb = tboxes + t * 6;
    float tcx = tb[0], tcy = tb[1], tl = tb[2], tr = tb[3], ttp = tb[4], tbo = tb[5];

    float cost_class = g_focal[q * NC + labels[t]];

    float c3d   = fabsf(cx - tcx) + fabsf(cy - tcy);
    float cbbox = fabsf(l - tl) + fabsf(r - tr) + fabsf(tp - ttp) + fabsf(bo - tbo);

    float ax0 = cx - l,   ay0 = cy - tp,   ax1 = cx + r,   ay1 = cy + bo;
    float bx0 = tcx - tl, by0 = tcy - ttp, bx1 = tcx + tr, by1 = tcy + tbo;
    float a1 = (ax1 - ax0) * (ay1 - ay0);
    float a2 = (bx1 - bx0) * (by1 - by0);
    float iw = fmaxf(fminf(ax1, bx1) - fmaxf(ax0, bx0), 0.0f);
    float ih = fmaxf(fminf(ay1, by1) - fmaxf(ay0, by0), 0.0f);
    float inter = iw * ih;
    float uni = a1 + a2 - inter;
    float iou = inter / uni;
    float ew = fmaxf(fmaxf(ax1, bx1) - fminf(ax0, bx0), 0.0f);
    float eh = fmaxf(fmaxf(ay1, by1) - fminf(ay0, by0), 0.0f);
    float ae = ew * eh;
    float giou = iou - (ae - uni) / ae;

    return 5.0f * cbbox + 10.0f * c3d + 2.0f * cost_class + 2.0f * (-giou);
}

// monotone f64 <-> uint64 key (order-preserving)
__device__ __forceinline__ unsigned long long dkey(double d) {
    long long ll = __double_as_longlong(d);
    return (unsigned long long)(ll ^ ((ll >> 63) | 0x8000000000000000LL));
}
__device__ __forceinline__ double dunkey(unsigned long long k) {
    long long kl = (long long)k;
    kl ^= (((~kl) >> 63) | 0x8000000000000000LL);
    return __longlong_as_double(kl);
}

// ---------------------------------------------------------------------------
// Fused kernel: blocks [0, NPROB) run JV-LSA (computing their own 48x50 tile),
// blocks [NPROB, NPROB+COST_BLOCKS) fill the full cost matrix C.
// Both cohorts run concurrently in one launch.
// ---------------------------------------------------------------------------
__global__ void __launch_bounds__(256)
fused_kernel(const float* __restrict__ pboxes,   // (BS*NQ, 6)
             const int*   __restrict__ labels,   // (NTOT)
             const float* __restrict__ tboxes,   // (NTOT, 6)
             float* __restrict__ C,               // (BS*NQ, NTOT)
             float* __restrict__ pi_out,          // (BS, NMATCH)
             float* __restrict__ ti_out,
             int do_lsa)
{
    // ---------------- cost-matrix cohort ----------------
    if (blockIdx.x >= NPROB) {
        int cb = blockIdx.x - NPROB;
        int base = (cb * 256 + threadIdx.x) * 4;   // 4 consecutive t, same q
        int q = base / NTOT;
        int t0 = base - q * NTOT;
        const float* qb = pboxes + q * 6;
        float cx = qb[0], cy = qb[1], l = qb[2], r = qb[3], tp = qb[4], bo = qb[5];
        float4 out;
        out.x = cost_eval(cx, cy, l, r, tp, bo, q, t0 + 0, labels, tboxes);
        out.y = cost_eval(cx, cy, l, r, tp, bo, q, t0 + 1, labels, tboxes);
        out.z = cost_eval(cx, cy, l, r, tp, bo, q, t0 + 2, labels, tboxes);
        out.w = cost_eval(cx, cy, l, r, tp, bo, q, t0 + 3, labels, tboxes);
        *(float4*)&C[base] = out;
        return;
    }

    // ---------------- LSA cohort ----------------
    if (!do_lsa) return;
    int prob = blockIdx.x;
    int b = prob / GN;
    int g = prob - b * GN;
    int tid = threadIdx.x;

    __shared__ float costp[LSA_N][64];      // [row i][col jj], lane's 2 cols adjacent
    __shared__ double u_s[LSA_N + 1];
    __shared__ int p_s[LSA_M + 1];
    __shared__ int way_s[LSA_M + 1];

    // all 256 threads compute the 48x50 diagonal tile
    for (int idx = tid; idx < LSA_N * LSA_M; idx += 256) {
        int jj = idx / LSA_N;
        int i  = idx - jj * LSA_N;
        int q = b * NQ + g * GQ + jj;
        const float* qb = pboxes + q * 6;
        costp[i][jj] = cost_eval(qb[0], qb[1], qb[2], qb[3], qb[4], qb[5],
                                 q, b * NT + i, labels, tboxes);
    }
    if (tid <= LSA_N) u_s[tid] = 0.0;
    if (tid >= 64 && tid < 64 + LSA_M + 1) { p_s[tid - 64] = 0; way_s[tid - 64] = 0; }
    __syncthreads();
    if (tid >= 32) return;

    int lane = tid;
    const bool act = (lane < 25);
    const int colA = 2 * lane + 1;          // 1-based owned columns
    const int colB = 2 * lane + 2;
    const unsigned long long KINF = 0xFFF0000000000000ULL;  // dkey(+inf)
    double v0 = 0.0, v1 = 0.0;
    int pr0 = 0, pr1 = 0;                   // register mirror of p for my cols

    for (int i = 1; i <= LSA_N; i++) {
        double m0 = INFINITY, m1 = INFINITY;
        unsigned long long k0 = act ? KINF : ~0ULL;
        unsigned long long k1 = k0;
        unsigned used2 = act ? 0u : 3u;
        double u0r = 0.0, u1r = 0.0;        // phase-cached u of my assigned rows
        if (act) { u0r = u_s[pr0]; u1r = u_s[pr1]; }   // u_s[0] == 0 always
        double uirow = u_s[i];              // u of current row (accumulates deltas)
        double ui0 = uirow;                 // u[i0] for the scan (phase-start value)
        int i0 = i;
        int j0 = 0;

        while (true) {
            // relax free columns from row i0
            float2 cf = *(const float2*)&costp[i0 - 1][2 * lane];
            if (act) {
                if (!(used2 & 1u)) {
                    double cur = ((double)cf.x - ui0) - v0;
                    unsigned long long kc = dkey(cur);
                    if (kc < k0) { m0 = cur; k0 = kc; way_s[colA] = j0; }
                }
                if (!(used2 & 2u)) {
                    double cur = ((double)cf.y - ui0) - v1;
                    unsigned long long kc = dkey(cur);
                    if (kc < k1) { m1 = cur; k1 = kc; way_s[colB] = j0; }
                }
            }

            // lane-local best (tie -> colA, the smaller index)
            unsigned long long ka = (used2 & 1u) ? ~0ULL : k0;
            unsigned long long kb = (used2 & 2u) ? ~0ULL : k1;
            unsigned long long bk; unsigned bj;
            if (ka <= kb) { bk = ka; bj = (unsigned)colA; }
            else          { bk = kb; bj = (unsigned)colB; }

            // warp argmin via 3 redux.min.u32 (lexicographic hi, lo, col)
            unsigned hi = (unsigned)(bk >> 32);
            unsigned hmin = __reduce_min_sync(FULLMASK, hi);
            unsigned lo = (hi == hmin) ? (unsigned)bk : 0xFFFFFFFFu;
            unsigned lmin = __reduce_min_sync(FULLMASK, lo);
            bool elig = (hi == hmin) && ((unsigned)bk == lmin);
            unsigned jcand = elig ? bj : 0xFFu;
            unsigned jmin = __reduce_min_sync(FULLMASK, jcand);
            double delta = dunkey(((unsigned long long)hmin << 32) | lmin);

            // dual / minv updates (reference op order preserved)
            if (act) {
                if (used2 & 1u) { v0 -= delta; u0r += delta; }
                else            { m0 -= delta; k0 = dkey(m0); }
                if (used2 & 2u) { v1 -= delta; u1r += delta; }
                else            { m1 -= delta; k1 = dkey(m1); }
            }
            uirow += delta;   // u[p[0]] = u[i] += delta (same on all lanes)

            // fetch p[jmin] and phase-start u of its row from the owner lane
            int parB  = (int)((jmin - 1) & 1u);
            int owner = (int)((jmin - 1) >> 1);
            int    selp = parB ? pr1 : pr0;
            double selu = parB ? u1r : u0r;   // jmin not yet used -> phase-start value
            int    pval = __shfl_sync(FULLMASK, selp, owner);
            double un   = __shfl_sync(FULLMASK, selu, owner);

            j0 = (int)jmin;
            if (pval == 0) break;             // reached a free column
            if (lane == owner) used2 |= 1u << parB;
            i0 = pval;
            ui0 = un;
        }

        // write back u (same accumulation sequence as reference)
        if (act) {
            if (used2 & 1u) u_s[pr0] = u0r;
            if (used2 & 2u) u_s[pr1] = u1r;
        }
        if (lane == 0) u_s[i] = uirow;
        __syncwarp();

        // augment alternating path
        if (lane == 0) {
            int jc = j0;
            while (jc) {
                int jn = way_s[jc];
                p_s[jc] = (jn == 0) ? i : p_s[jn];
                jc = jn;
            }
        }
        __syncwarp();
        if (act) { pr0 = p_s[colA]; pr1 = p_s[colB]; }
    }

    // Emit matches: queries ascending (48 of 50 columns assigned)
    if (lane == 0) {
        int base = b * NMATCH + g * NT;
        int k = 0;
        for (int j = 1; j <= LSA_M; j++) {
            int pj = p_s[j];
            if (pj) {
                pi_out[base + k] = (float)(g * GQ + j - 1);
                ti_out[base + k] = (float)(pj - 1);
                k++;
            }
        }
    }
}

// ---------------------------------------------------------------------------
extern "C" void kernel_launch(void* const* d_in, const int* in_sizes, int n_in,
                              void* d_out, int out_size)
{
    const float* logits = (const float*)d_in[0];  // (16,550,91)
    const float* pboxes = (const float*)d_in[1];  // (16,550,6)
    const int*   labels = (const int*)  d_in[2];  // (16,48)
    const float* tboxes = (const float*)d_in[3];  // (16,48,6)

    float* C  = (float*)d_out;
    const int C_ELEMS = BS * NQ * NTOT;          // 6,758,400
    float* pi = C + C_ELEMS;
    float* ti = pi + BS * NMATCH;

    int nfoc = BS * NQ * NC;
    focal_kernel<<<(nfoc + 255) / 256, 256>>>(logits);

    int do_lsa = (out_size >= C_ELEMS + 2 * BS * NMATCH) ? 1 : 0;
    fused_kernel<<<NPROB + COST_BLOCKS, 256>>>(pboxes, labels, tboxes,
                                               C, pi, ti, do_lsa);
}

// round 8
// speedup vs baseline: 4.5248x; 1.8101x over previous
#include <cuda_runtime.h>
#include <math.h>

// Problem constants (fixed by setup_inputs)
#define BS   16
#define NQ   550
#define NC   91
#define NT   48
#define GN   11
#define GQ   (NQ / GN)       // 50
#define NTOT (BS * NT)       // 768
#define NMATCH (GN * NT)     // 528

#define LSA_N 48   // rows (targets) of transposed problem
#define LSA_M 50   // cols (queries)
#define NPROB (BS * GN)      // 176 LSA problems
#define COST_BLOCKS 6600     // 6,758,400 / (256*4)
#define FULLMASK 0xffffffffu

#define SCALE_D 17592186044416.0    // 2^44 fixed-point scale
#define LL_INF  0x7FFFFFFFFFFFFFFFLL

// scratch: focal class cost per (q, class)
__device__ float g_focal[BS * NQ * NC];

// ---------------------------------------------------------------------------
// Kernel 0: focal class cost per (query, class)
// ---------------------------------------------------------------------------
__global__ void focal_kernel(const float* __restrict__ logits)
{
    int idx = blockIdx.x * blockDim.x + threadIdx.x;
    if (idx >= BS * NQ * NC) return;
    float x = logits[idx];
    float p = 1.0f / (1.0f + expf(-x));
    float omp = 1.0f - p;
    float pos = 0.25f * omp * omp * (-logf(p + 1e-8f));
    float neg = 0.75f * p * p * (-logf(omp + 1e-8f));
    g_focal[idx] = pos - neg;
}

// ---------------------------------------------------------------------------
// Shared cost evaluation (identical expression everywhere)
// ---------------------------------------------------------------------------
__device__ __forceinline__ float cost_eval(
    float cx, float cy, float l, float r, float tp, float bo,
    int q, int t,
    const int* __restrict__ labels, const float* __restrict__ tboxes)
{
    const float* tb = tboxes + t * 6;
    float tcx = tb[0], tcy = tb[1], tl = tb[2], tr = tb[3], ttp = tb[4], tbo = tb[5];

    float cost_class = g_focal[q * NC + labels[t]];

    float c3d   = fabsf(cx - tcx) + fabsf(cy - tcy);
    float cbbox = fabsf(l - tl) + fabsf(r - tr) + fabsf(tp - ttp) + fabsf(bo - tbo);

    float ax0 = cx - l,   ay0 = cy - tp,   ax1 = cx + r,   ay1 = cy + bo;
    float bx0 = tcx - tl, by0 = tcy - ttp, bx1 = tcx + tr, by1 = tcy + tbo;
    float a1 = (ax1 - ax0) * (ay1 - ay0);
    float a2 = (bx1 - bx0) * (by1 - by0);
    float iw = fmaxf(fminf(ax1, bx1) - fmaxf(ax0, bx0), 0.0f);
    float ih = fmaxf(fminf(ay1, by1) - fmaxf(ay0, by0), 0.0f);
    float inter = iw * ih;
    float uni = a1 + a2 - inter;
    float iou = inter / uni;
    float ew = fmaxf(fmaxf(ax1, bx1) - fminf(ax0, bx0), 0.0f);
    float eh = fmaxf(fmaxf(ay1, by1) - fminf(ay0, by0), 0.0f);
    float ae = ew * eh;
    float giou = iou - (ae - uni) / ae;

    return 5.0f * cbbox + 10.0f * c3d + 2.0f * cost_class + 2.0f * (-giou);
}

// ---------------------------------------------------------------------------
// Fused kernel: blocks [0, NPROB) run JV-LSA in s64 fixed-point,
// blocks [NPROB, ...) fill the full cost matrix C. Concurrent in one launch.
// ---------------------------------------------------------------------------
__global__ void __launch_bounds__(256)
fused_kernel(const float* __restrict__ pboxes,
             const int*   __restrict__ labels,
             const float* __restrict__ tboxes,
             float* __restrict__ C,
             float* __restrict__ pi_out,
             float* __restrict__ ti_out,
             int do_lsa)
{
    // ---------------- cost-matrix cohort ----------------
    if (blockIdx.x >= NPROB) {
        int cb = blockIdx.x - NPROB;
        int base = (cb * 256 + threadIdx.x) * 4;
        int q = base / NTOT;
        int t0 = base - q * NTOT;
        const float* qb = pboxes + q * 6;
        float cx = qb[0], cy = qb[1], l = qb[2], r = qb[3], tp = qb[4], bo = qb[5];
        float4 out;
        out.x = cost_eval(cx, cy, l, r, tp, bo, q, t0 + 0, labels, tboxes);
        out.y = cost_eval(cx, cy, l, r, tp, bo, q, t0 + 1, labels, tboxes);
        out.z = cost_eval(cx, cy, l, r, tp, bo, q, t0 + 2, labels, tboxes);
        out.w = cost_eval(cx, cy, l, r, tp, bo, q, t0 + 3, labels, tboxes);
        *(float4*)&C[base] = out;
        return;
    }

    // ---------------- LSA cohort ----------------
    if (!do_lsa) return;
    int prob = blockIdx.x;
    int b = prob / GN;
    int g = prob - b * GN;
    int tid = threadIdx.x;

    __shared__ long long costp[LSA_N][64];   // fixed-point costs, 2 cols/lane adjacent
    __shared__ long long u_s[LSA_N + 1];
    __shared__ int p_s[LSA_M + 1];
    __shared__ int way_s[LSA_M + 1];

    // all 256 threads compute + quantize the 48x50 diagonal tile
    for (int idx = tid; idx < LSA_N * LSA_M; idx += 256) {
        int jj = idx / LSA_N;
        int i  = idx - jj * LSA_N;
        int q = b * NQ + g * GQ + jj;
        const float* qb = pboxes + q * 6;
        float c = cost_eval(qb[0], qb[1], qb[2], qb[3], qb[4], qb[5],
                            q, b * NT + i, labels, tboxes);
        costp[i][jj] = __double2ll_rn((double)c * SCALE_D);
    }
    if (tid <= LSA_N) u_s[tid] = 0LL;
    if (tid >= 64 && tid < 64 + LSA_M + 1) { p_s[tid - 64] = 0; way_s[tid - 64] = 0; }
    __syncthreads();
    if (tid >= 32) return;

    int lane = tid;
    const bool act = (lane < 25);
    const int colA = 2 * lane + 1;          // 1-based owned columns
    const int colB = 2 * lane + 2;
    long long v0 = 0, v1 = 0;
    int pr0 = 0, pr1 = 0;                   // register mirror of p for my cols

    for (int i = 1; i <= LSA_N; i++) {
        long long m0 = LL_INF, m1 = LL_INF;
        unsigned used2 = act ? 0u : 3u;
        long long u0r = u_s[pr0];           // phase-start u of my assigned rows
        long long u1r = u_s[pr1];           // (u_s[0] == 0 always)
        long long uirow = u_s[i];
        long long ui0 = uirow;
        int i0 = i;
        int j0 = 0;

        while (true) {
            // relax free columns from row i0 (exact integer arithmetic)
            longlong2 cf = *(const longlong2*)&costp[i0 - 1][2 * lane];
            if (act) {
                if (!(used2 & 1u)) {
                    long long cur = cf.x - ui0 - v0;
                    if (cur < m0) { m0 = cur; way_s[colA] = j0; }
                }
                if (!(used2 & 2u)) {
                    long long cur = cf.y - ui0 - v1;
                    if (cur < m1) { m1 = cur; way_s[colB] = j0; }
                }
            }

            // lane-local best (tie -> colA, the smaller index)
            long long ca = (used2 & 1u) ? LL_INF : m0;
            long long cb = (used2 & 2u) ? LL_INF : m1;
            bool pickA = (ca <= cb);
            long long mb = pickA ? ca : cb;
            unsigned bj = pickA ? (unsigned)colA : (unsigned)colB;
            int psel    = pickA ? pr0 : pr1;
            unsigned long long bk = (unsigned long long)mb ^ 0x8000000000000000ULL;

            // warp argmin via 3 redux.min.u32 (hi, lo, then packed (col,p[col]))
            unsigned hi = (unsigned)(bk >> 32);
            unsigned hmin = __reduce_min_sync(FULLMASK, hi);
            unsigned lo = (hi == hmin) ? (unsigned)bk : 0xFFFFFFFFu;
            unsigned lmin = __reduce_min_sync(FULLMASK, lo);
            bool elig = (hi == hmin) && ((unsigned)bk == lmin);
            unsigned pk = elig ? ((bj << 6) | (unsigned)psel) : 0xFFFFFFFFu;
            unsigned pkm = __reduce_min_sync(FULLMASK, pk);
            unsigned jmin = pkm >> 6;
            int pval = (int)(pkm & 63u);
            long long delta = (long long)((((unsigned long long)hmin << 32) | lmin)
                                          ^ 0x8000000000000000ULL);

            // dual / minv updates (exact; relax precedes, so free m are finite)
            if (act) {
                if (used2 & 1u) { v0 -= delta; u0r += delta; } else { m0 -= delta; }
                if (used2 & 2u) { v1 -= delta; u1r += delta; } else { m1 -= delta; }
            }
            uirow += delta;

            j0 = (int)jmin;
            if (pval == 0) break;             // reached a free column
            if (lane == (int)((jmin - 1) >> 1)) used2 |= 1u << ((jmin - 1) & 1u);
            i0 = pval;
            ui0 = u_s[pval];                  // phase-start value (u_s untouched in-phase)
        }

        // write back u (same accumulation sequence as reference)
        if (act) {
            if (used2 & 1u) u_s[pr0] = u0r;
            if (used2 & 2u) u_s[pr1] = u1r;
        }
        if (lane == 0) u_s[i] = uirow;
        __syncwarp();

        // augment alternating path
        if (lane == 0) {
            int jc = j0;
            while (jc) {
                int jn = way_s[jc];
                p_s[jc] = (jn == 0) ? i : p_s[jn];
                jc = jn;
            }
        }
        __syncwarp();
        if (act) { pr0 = p_s[colA]; pr1 = p_s[colB]; }
        __syncwarp();
    }

    // Emit matches: queries ascending (48 of 50 columns assigned)
    if (lane == 0) {
        int base = b * NMATCH + g * NT;
        int k = 0;
        for (int j = 1; j <= LSA_M; j++) {
            int pj = p_s[j];
            if (pj) {
                pi_out[base + k] = (float)(g * GQ + j - 1);
                ti_out[base + k] = (float)(pj - 1);
                k++;
            }
        }
    }
}

// ---------------------------------------------------------------------------
extern "C" void kernel_launch(void* const* d_in, const int* in_sizes, int n_in,
                              void* d_out, int out_size)
{
    const float* logits = (const float*)d_in[0];  // (16,550,91)
    const float* pboxes = (const float*)d_in[1];  // (16,550,6)
    const int*   labels = (const int*)  d_in[2];  // (16,48)
    const float* tboxes = (const float*)d_in[3];  // (16,48,6)

    float* C  = (float*)d_out;
    const int C_ELEMS = BS * NQ * NTOT;          // 6,758,400
    float* pi = C + C_ELEMS;
    float* ti = pi + BS * NMATCH;

    int nfoc = BS * NQ * NC;
    focal_kernel<<<(nfoc + 255) / 256, 256>>>(logits);

    int do_lsa = (out_size >= C_ELEMS + 2 * BS * NMATCH) ? 1 : 0;
    fused_kernel<<<NPROB + COST_BLOCKS, 256>>>(pboxes, labels, tboxes,
                                               C, pi, ti, do_lsa);
}

// round 9
// speedup vs baseline: 4.9009x; 1.0831x over previous
#include <cuda_runtime.h>
#include <math.h>

// Problem constants (fixed by setup_inputs)
#define BS   16
#define NQ   550
#define NC   91
#define NT   48
#define GN   11
#define GQ   (NQ / GN)       // 50
#define NTOT (BS * NT)       // 768
#define NMATCH (GN * NT)     // 528

#define LSA_N 48   // rows (targets) of transposed problem
#define LSA_M 50   // cols (queries)
#define NPROB (BS * GN)      // 176 LSA problems
#define COST_BLOCKS 6600     // 6,758,400 / (256*4)
#define FULLMASK 0xffffffffu

#define SCALE39 549755813888.0      // 2^39 fixed-point scale
#define BIAS51  (1LL << 51)
#define LL_INF  0x7FFFFFFFFFFFFFFFLL

// scratch: focal class cost per (q, class)
__device__ float g_focal[BS * NQ * NC];

// ---------------------------------------------------------------------------
// Kernel 0: focal class cost per (query, class)
// ---------------------------------------------------------------------------
__global__ void focal_kernel(const float* __restrict__ logits)
{
    int idx = blockIdx.x * blockDim.x + threadIdx.x;
    if (idx >= BS * NQ * NC) return;
    float x = logits[idx];
    float p = 1.0f / (1.0f + expf(-x));
    float omp = 1.0f - p;
    float pos = 0.25f * omp * omp * (-logf(p + 1e-8f));
    float neg = 0.75f * p * p * (-logf(omp + 1e-8f));
    g_focal[idx] = pos - neg;
}

// ---------------------------------------------------------------------------
// Shared cost evaluation (identical expression everywhere)
// ---------------------------------------------------------------------------
__device__ __forceinline__ float cost_eval(
    float cx, float cy, float l, float r, float tp, float bo,
    int q, int t,
    const int* __restrict__ labels, const float* __restrict__ tboxes)
{
    const float* tb = tboxes + t * 6;
    float tcx = tb[0], tcy = tb[1], tl = tb[2], tr = tb[3], ttp = tb[4], tbo = tb[5];

    float cost_class = g_focal[q * NC + labels[t]];

    float c3d   = fabsf(cx - tcx) + fabsf(cy - tcy);
    float cbbox = fabsf(l - tl) + fabsf(r - tr) + fabsf(tp - ttp) + fabsf(bo - tbo);

    float ax0 = cx - l,   ay0 = cy - tp,   ax1 = cx + r,   ay1 = cy + bo;
    float bx0 = tcx - tl, by0 = tcy - ttp, bx1 = tcx + tr, by1 = tcy + tbo;
    float a1 = (ax1 - ax0) * (ay1 - ay0);
    float a2 = (bx1 - bx0) * (by1 - by0);
    float iw = fmaxf(fminf(ax1, bx1) - fmaxf(ax0, bx0), 0.0f);
    float ih = fmaxf(fminf(ay1, by1) - fmaxf(ay0, by0), 0.0f);
    float inter = iw * ih;
    float uni = a1 + a2 - inter;
    float iou = inter / uni;
    float ew = fmaxf(fmaxf(ax1, bx1) - fminf(ax0, bx0), 0.0f);
    float eh = fmaxf(fmaxf(ay1, by1) - fminf(ay0, by0), 0.0f);
    float ae = ew * eh;
    float giou = iou - (ae - uni) / ae;

    return 5.0f * cbbox + 10.0f * c3d + 2.0f * cost_class + 2.0f * (-giou);
}

// ---------------------------------------------------------------------------
// Fused kernel: blocks [0, NPROB) run JV-LSA (s64 fixed-point, warm start),
// blocks [NPROB, ...) fill the full cost matrix C. Concurrent in one launch.
// ---------------------------------------------------------------------------
__global__ void __launch_bounds__(256)
fused_kernel(const float* __restrict__ pboxes,
             const int*   __restrict__ labels,
             const float* __restrict__ tboxes,
             float* __restrict__ C,
             float* __restrict__ pi_out,
             float* __restrict__ ti_out,
             int do_lsa)
{
    // ---------------- cost-matrix cohort ----------------
    if (blockIdx.x >= NPROB) {
        int cb = blockIdx.x - NPROB;
        int base = (cb * 256 + threadIdx.x) * 4;
        int q = base / NTOT;
        int t0 = base - q * NTOT;
        const float* qb = pboxes + q * 6;
        float cx = qb[0], cy = qb[1], l = qb[2], r = qb[3], tp = qb[4], bo = qb[5];
        float4 out;
        out.x = cost_eval(cx, cy, l, r, tp, bo, q, t0 + 0, labels, tboxes);
        out.y = cost_eval(cx, cy, l, r, tp, bo, q, t0 + 1, labels, tboxes);
        out.z = cost_eval(cx, cy, l, r, tp, bo, q, t0 + 2, labels, tboxes);
        out.w = cost_eval(cx, cy, l, r, tp, bo, q, t0 + 3, labels, tboxes);
        *(float4*)&C[base] = out;
        return;
    }

    // ---------------- LSA cohort ----------------
    if (!do_lsa) return;
    int prob = blockIdx.x;
    int b = prob / GN;
    int g = prob - b * GN;
    int tid = threadIdx.x;

    __shared__ long long costp[LSA_N][64];   // fixed-point costs, 2 cols/lane adjacent
    __shared__ long long u_s[LSA_N + 1];
    __shared__ int p_s[LSA_M + 1];
    __shared__ int way_s[LSA_M + 1];
    __shared__ int rowmin_j[LSA_N + 1];
    __shared__ int claim[LSA_M + 1];
    __shared__ int row_done[LSA_N + 1];

    // all 256 threads compute + quantize the 48x50 diagonal tile
    for (int idx = tid; idx < LSA_N * LSA_M; idx += 256) {
        int jj = idx / LSA_N;
        int i  = idx - jj * LSA_N;
        int q = b * NQ + g * GQ + jj;
        const float* qb = pboxes + q * 6;
        float c = cost_eval(qb[0], qb[1], qb[2], qb[3], qb[4], qb[5],
                            q, b * NT + i, labels, tboxes);
        costp[i][jj] = __double2ll_rn((double)c * SCALE39);
    }
    if (tid >= 64 && tid < 64 + LSA_M + 1) {
        p_s[tid - 64] = 0; way_s[tid - 64] = 0; claim[tid - 64] = 1 << 30;
    }
    if (tid == 63) u_s[0] = 0LL;
    __syncthreads();

    // warm start: u[i] = row min (exact), greedy claim of argmin columns
    if (tid < LSA_N) {
        int i = tid;
        long long bestk = LL_INF;
        #pragma unroll 1
        for (int s = 0; s < LSA_M; s++) {
            int jj = i + s; if (jj >= LSA_M) jj -= LSA_M;   // staggered, conflict-free
            long long kk = ((costp[i][jj] + BIAS51) << 6) | jj;  // tie -> smaller j
            if (kk < bestk) bestk = kk;
        }
        int jarg = (int)(bestk & 63);
        u_s[i + 1] = (bestk >> 6) - BIAS51;
        rowmin_j[i + 1] = jarg + 1;
        row_done[i + 1] = 0;
        atomicMin(&claim[jarg + 1], i + 1);    // smallest row wins = row-order greedy
    }
    __syncthreads();
    if (tid < LSA_N) {
        int i = tid + 1;
        int j = rowmin_j[i];
        if (claim[j] == i) { p_s[j] = i; row_done[i] = 1; }  // tight edge (c-u-v = 0)
    }
    __syncthreads();
    if (tid >= 32) return;

    int lane = tid;
    const bool act = (lane < 25);
    const int colA = 2 * lane + 1;          // 1-based owned columns
    const int colB = 2 * lane + 2;
    long long v0 = 0, v1 = 0;
    int pr0 = 0, pr1 = 0;
    if (act) { pr0 = p_s[colA]; pr1 = p_s[colB]; }

    for (int i = 1; i <= LSA_N; i++) {
        if (row_done[i]) continue;          // pre-matched by greedy

        long long m0 = LL_INF, m1 = LL_INF;
        unsigned used2 = act ? 0u : 3u;
        long long u0r = u_s[pr0];           // phase-start u of my assigned rows
        long long u1r = u_s[pr1];           // (u_s[0] == 0 always)
        long long uirow = u_s[i];
        long long ui0 = uirow;
        int i0 = i;
        int j0 = 0;

        while (true) {
            // relax free columns from row i0 (exact integer arithmetic)
            longlong2 cf = *(const longlong2*)&costp[i0 - 1][2 * lane];
            if (act) {
                if (!(used2 & 1u)) {
                    long long cur = cf.x - ui0 - v0;
                    if (cur < m0) { m0 = cur; way_s[colA] = j0; }
                }
                if (!(used2 & 2u)) {
                    long long cur = cf.y - ui0 - v1;
                    if (cur < m1) { m1 = cur; way_s[colB] = j0; }
                }
            }

            // lane-local best (tie -> colA, the smaller index)
            long long ca = (used2 & 1u) ? LL_INF : m0;
            long long cb2 = (used2 & 2u) ? LL_INF : m1;
            bool pickA = (ca <= cb2);
            long long mb = pickA ? ca : cb2;
            unsigned bj = pickA ? (unsigned)colA : (unsigned)colB;
            int psel    = pickA ? pr0 : pr1;

            // 52-bit key: |reduced cost| < 2^12 at scale 2^-39 -> val+2^51 < 2^52
            unsigned hi, packv;
            if (mb >= BIAS51) { hi = 0xFFFFFFFFu; packv = 0xFFFFFFFFu; }
            else {
                unsigned long long key = (unsigned long long)(mb + BIAS51);
                hi = (unsigned)(key >> 20);
                packv = (((unsigned)key & 0xFFFFFu) << 12) | (bj << 6) | (unsigned)psel;
            }

            // warp argmin via 2 redux.min.u32 (hi32, then (lo20, col, p[col]))
            unsigned hmin = __reduce_min_sync(FULLMASK, hi);
            unsigned pk = (hi == hmin) ? packv : 0xFFFFFFFFu;
            unsigned pkm = __reduce_min_sync(FULLMASK, pk);
            unsigned jmin = (pkm >> 6) & 63u;
            int pval = (int)(pkm & 63u);
            long long delta = (long long)((((unsigned long long)hmin << 20) | (pkm >> 12)))
                              - BIAS51;

            // dual / minv updates (exact)
            if (act) {
                if (used2 & 1u) { v0 -= delta; u0r += delta; } else { m0 -= delta; }
                if (used2 & 2u) { v1 -= delta; u1r += delta; } else { m1 -= delta; }
            }
            uirow += delta;

            j0 = (int)jmin;
            if (pval == 0) break;             // reached a free column
            if (lane == (int)((jmin - 1) >> 1)) used2 |= 1u << ((jmin - 1) & 1u);
            i0 = pval;
            ui0 = u_s[pval];                  // phase-start value (u_s untouched in-phase)
        }

        // write back u
        if (act) {
            if (used2 & 1u) u_s[pr0] = u0r;
            if (used2 & 2u) u_s[pr1] = u1r;
        }
        if (lane == 0) u_s[i] = uirow;
        __syncwarp();

        // augment alternating path
        if (lane == 0) {
            int jc = j0;
            while (jc) {
                int jn = way_s[jc];
                p_s[jc] = (jn == 0) ? i : p_s[jn];
                jc = jn;
            }
        }
        __syncwarp();
        if (act) { pr0 = p_s[colA]; pr1 = p_s[colB]; }
        __syncwarp();
    }

    // Emit matches: queries ascending (48 of 50 columns assigned)
    if (lane == 0) {
        int base = b * NMATCH + g * NT;
        int k = 0;
        for (int j = 1; j <= LSA_M; j++) {
            int pj = p_s[j];
            if (pj) {
                pi_out[base + k] = (float)(g * GQ + j - 1);
                ti_out[base + k] = (float)(pj - 1);
                k++;
            }
        }
    }
}

// ---------------------------------------------------------------------------
extern "C" void kernel_launch(void* const* d_in, const int* in_sizes, int n_in,
                              void* d_out, int out_size)
{
    const float* logits = (const float*)d_in[0];  // (16,550,91)
    const float* pboxes = (const float*)d_in[1];  // (16,550,6)
    const int*   labels = (const int*)  d_in[2];  // (16,48)
    const float* tboxes = (const float*)d_in[3];  // (16,48,6)

    float* C  = (float*)d_out;
    const int C_ELEMS = BS * NQ * NTOT;          // 6,758,400
    float* pi = C + C_ELEMS;
    float* ti = pi + BS * NMATCH;

    int nfoc = BS * NQ * NC;
    focal_kernel<<<(nfoc + 255) / 256, 256>>>(logits);

    int do_lsa = (out_size >= C_ELEMS + 2 * BS * NMATCH) ? 1 : 0;
    fused_kernel<<<NPROB + COST_BLOCKS, 256>>>(pboxes, labels, tboxes,
                                               C, pi, ti, do_lsa);
}

// round 10
// speedup vs baseline: 5.4249x; 1.1069x over previous
#include <cuda_runtime.h>
#include <math.h>

// Problem constants (fixed by setup_inputs)
#define BS   16
#define NQ   550
#define NC   91
#define NT   48
#define GN   11
#define GQ   (NQ / GN)       // 50
#define NTOT (BS * NT)       // 768
#define NMATCH (GN * NT)     // 528

#define LSA_N 48   // rows (targets) of transposed problem
#define LSA_M 50   // cols (queries)
#define NPROB (BS * GN)      // 176 LSA problems
#define COST_BLOCKS 6600     // 6,758,400 / (256*4)
#define FULLMASK 0xffffffffu

#define SCALE39 549755813888.0      // 2^39 fixed-point scale
#define BIAS51  (1LL << 51)
#define LL_INF  0x7FFFFFFFFFFFFFFFLL

// scratch: focal class cost per (q, class)
__device__ float g_focal[BS * NQ * NC];

// ---------------------------------------------------------------------------
// Kernel 0: focal class cost per (query, class)
// ---------------------------------------------------------------------------
__global__ void focal_kernel(const float* __restrict__ logits)
{
    int idx = blockIdx.x * blockDim.x + threadIdx.x;
    if (idx >= BS * NQ * NC) return;
    float x = logits[idx];
    float p = 1.0f / (1.0f + expf(-x));
    float omp = 1.0f - p;
    float pos = 0.25f * omp * omp * (-logf(p + 1e-8f));
    float neg = 0.75f * p * p * (-logf(omp + 1e-8f));
    g_focal[idx] = pos - neg;
}

// ---------------------------------------------------------------------------
// Shared cost evaluation (identical expression everywhere)
// ---------------------------------------------------------------------------
__device__ __forceinline__ float cost_eval(
    float cx, float cy, float l, float r, float tp, float bo,
    int q, int t,
    const int* __restrict__ labels, const float* __restrict__ tboxes)
{
    const float* tb = tboxes + t * 6;
    float tcx = tb[0], tcy = tb[1], tl = tb[2], tr = tb[3], ttp = tb[4], tbo = tb[5];

    float cost_class = g_focal[q * NC + labels[t]];

    float c3d   = fabsf(cx - tcx) + fabsf(cy - tcy);
    float cbbox = fabsf(l - tl) + fabsf(r - tr) + fabsf(tp - ttp) + fabsf(bo - tbo);

    float ax0 = cx - l,   ay0 = cy - tp,   ax1 = cx + r,   ay1 = cy + bo;
    float bx0 = tcx - tl, by0 = tcy - ttp, bx1 = tcx + tr, by1 = tcy + tbo;
    float a1 = (ax1 - ax0) * (ay1 - ay0);
    float a2 = (bx1 - bx0) * (by1 - by0);
    float iw = fmaxf(fminf(ax1, bx1) - fmaxf(ax0, bx0), 0.0f);
    float ih = fmaxf(fminf(ay1, by1) - fmaxf(ay0, by0), 0.0f);
    float inter = iw * ih;
    float uni = a1 + a2 - inter;
    float iou = inter / uni;
    float ew = fmaxf(fmaxf(ax1, bx1) - fminf(ax0, bx0), 0.0f);
    float eh = fmaxf(fmaxf(ay1, by1) - fminf(ay0, by0), 0.0f);
    float ae = ew * eh;
    float giou = iou - (ae - uni) / ae;

    return 5.0f * cbbox + 10.0f * c3d + 2.0f * cost_class + 2.0f * (-giou);
}

// warp-min over 58-bit keys packed as ((val+BIAS51)<<6)|col ; ~0ULL = inactive
__device__ __forceinline__ unsigned long long warp_min58(unsigned long long key)
{
    unsigned hi = (unsigned)(key >> 32);
    unsigned hmin = __reduce_min_sync(FULLMASK, hi);
    unsigned lo = (hi == hmin) ? (unsigned)key : 0xFFFFFFFFu;
    unsigned lmin = __reduce_min_sync(FULLMASK, lo);
    return ((unsigned long long)hmin << 32) | lmin;
}

// ---------------------------------------------------------------------------
// Fused kernel: blocks [0, NPROB) run JV-LSA (s64 fixed-point, row-reduction
// + greedy + 2-pass augmenting-row-reduction + shortest-path phases),
// blocks [NPROB, ...) fill the full cost matrix C. Concurrent in one launch.
// ---------------------------------------------------------------------------
__global__ void __launch_bounds__(256)
fused_kernel(const float* __restrict__ pboxes,
             const int*   __restrict__ labels,
             const float* __restrict__ tboxes,
             float* __restrict__ C,
             float* __restrict__ pi_out,
             float* __restrict__ ti_out,
             int do_lsa)
{
    // ---------------- cost-matrix cohort ----------------
    if (blockIdx.x >= NPROB) {
        int cb = blockIdx.x - NPROB;
        int base = (cb * 256 + threadIdx.x) * 4;
        int q = base / NTOT;
        int t0 = base - q * NTOT;
        const float* qb = pboxes + q * 6;
        float cx = qb[0], cy = qb[1], l = qb[2], r = qb[3], tp = qb[4], bo = qb[5];
        float4 out;
        out.x = cost_eval(cx, cy, l, r, tp, bo, q, t0 + 0, labels, tboxes);
        out.y = cost_eval(cx, cy, l, r, tp, bo, q, t0 + 1, labels, tboxes);
        out.z = cost_eval(cx, cy, l, r, tp, bo, q, t0 + 2, labels, tboxes);
        out.w = cost_eval(cx, cy, l, r, tp, bo, q, t0 + 3, labels, tboxes);
        *(float4*)&C[base] = out;
        return;
    }

    // ---------------- LSA cohort ----------------
    if (!do_lsa) return;
    int prob = blockIdx.x;
    int b = prob / GN;
    int g = prob - b * GN;
    int tid = threadIdx.x;

    __shared__ long long costp[LSA_N][64];   // fixed-point costs, 2 cols/lane adjacent
    __shared__ long long u_s[LSA_N + 1];
    __shared__ int p_s[LSA_M + 1];
    __shared__ int way_s[LSA_M + 1];
    __shared__ int rowmin_j[LSA_N + 1];
    __shared__ int claim[LSA_M + 1];
    __shared__ int row_done[LSA_N + 1];

    // all 256 threads compute + quantize the 48x50 diagonal tile
    for (int idx = tid; idx < LSA_N * LSA_M; idx += 256) {
        int jj = idx / LSA_N;
        int i  = idx - jj * LSA_N;
        int q = b * NQ + g * GQ + jj;
        const float* qb = pboxes + q * 6;
        float c = cost_eval(qb[0], qb[1], qb[2], qb[3], qb[4], qb[5],
                            q, b * NT + i, labels, tboxes);
        costp[i][jj] = __double2ll_rn((double)c * SCALE39);
    }
    if (tid >= 64 && tid < 64 + LSA_M + 1) {
        p_s[tid - 64] = 0; way_s[tid - 64] = 0; claim[tid - 64] = 1 << 30;
    }
    if (tid == 63) u_s[0] = 0LL;
    __syncthreads();

    // warm start: u[i] = row min (exact), greedy claim of argmin columns
    if (tid < LSA_N) {
        int i = tid;
        long long bestk = LL_INF;
        #pragma unroll 1
        for (int s = 0; s < LSA_M; s++) {
            int jj = i + s; if (jj >= LSA_M) jj -= LSA_M;   // staggered, conflict-free
            long long kk = ((costp[i][jj] + BIAS51) << 6) | jj;  // tie -> smaller j
            if (kk < bestk) bestk = kk;
        }
        int jarg = (int)(bestk & 63);
        u_s[i + 1] = (bestk >> 6) - BIAS51;
        rowmin_j[i + 1] = jarg + 1;
        row_done[i + 1] = 0;
        atomicMin(&claim[jarg + 1], i + 1);    // smallest row wins = row-order greedy
    }
    __syncthreads();
    if (tid < LSA_N) {
        int i = tid + 1;
        int j = rowmin_j[i];
        if (claim[j] == i) { p_s[j] = i; row_done[i] = 1; }  // tight edge
    }
    __syncthreads();
    if (tid >= 32) return;

    int lane = tid;
    const bool act = (lane < 25);
    const int colA = 2 * lane + 1;          // 1-based owned columns
    const int colB = 2 * lane + 2;
    long long v0 = 0, v1 = 0;

    // ------- augmenting row reduction: exactly 2 passes over free rows -------
    for (int pass = 0; pass < 2; pass++) {
        for (int i = 1; i <= LSA_N; i++) {
            if (row_done[i]) continue;

            longlong2 cf = *(const longlong2*)&costp[i - 1][2 * lane];
            unsigned long long kA = ~0ULL, kB = ~0ULL;
            if (act) {
                kA = ((unsigned long long)(cf.x - v0 + BIAS51) << 6) | (unsigned)colA;
                kB = ((unsigned long long)(cf.y - v1 + BIAS51) << 6) | (unsigned)colB;
            }
            unsigned long long kloc = (kA <= kB) ? kA : kB;
            unsigned long long k1 = warp_min58(kloc);
            int j1 = (int)(k1 & 63u);
            long long val1 = (long long)(k1 >> 6) - BIAS51;

            unsigned long long kA2 = (colA == j1) ? ~0ULL : kA;
            unsigned long long kB2 = (colB == j1) ? ~0ULL : kB;
            unsigned long long kloc2 = (kA2 <= kB2) ? kA2 : kB2;
            unsigned long long k2 = warp_min58(kloc2);
            int j2 = (int)(k2 & 63u);
            long long val2 = (long long)(k2 >> 6) - BIAS51;

            int jsel = j1;
            if (val1 == val2 && p_s[j1] != 0) jsel = j2;   // tie: try second column
            int kdisp = p_s[jsel];
            __syncwarp();
            if (lane == 0) {
                p_s[jsel] = i;
                u_s[i] = val2;
                row_done[i] = 1;
                if (kdisp) row_done[kdisp] = 0;   // displaced row becomes free
            }
            if (val1 < val2) {                     // lower v[j1] so it stays tight
                int owner = (j1 - 1) >> 1;
                if (lane == owner) {
                    if ((j1 - 1) & 1) v1 -= (val2 - val1); else v0 -= (val2 - val1);
                }
            }
            __syncwarp();
        }
    }

    int pr0 = 0, pr1 = 0;
    if (act) { pr0 = p_s[colA]; pr1 = p_s[colB]; }
    __syncwarp();

    // ------- successive shortest-path phases for remaining free rows -------
    for (int i = 1; i <= LSA_N; i++) {
        if (row_done[i]) continue;

        long long m0 = LL_INF, m1 = LL_INF;
        unsigned used2 = act ? 0u : 3u;
        long long u0r = u_s[pr0];           // phase-start u of my assigned rows
        long long u1r = u_s[pr1];           // (u_s[0] == 0 always)
        long long uirow = u_s[i];
        long long ui0 = uirow;
        int i0 = i;
        int j0 = 0;

        while (true) {
            // relax free columns from row i0 (exact integer arithmetic)
            longlong2 cf = *(const longlong2*)&costp[i0 - 1][2 * lane];
            if (act) {
                if (!(used2 & 1u)) {
                    long long cur = cf.x - ui0 - v0;
                    if (cur < m0) { m0 = cur; way_s[colA] = j0; }
                }
                if (!(used2 & 2u)) {
                    long long cur = cf.y - ui0 - v1;
                    if (cur < m1) { m1 = cur; way_s[colB] = j0; }
                }
            }

            // lane-local best (tie -> colA, the smaller index)
            long long ca = (used2 & 1u) ? LL_INF : m0;
            long long cb2 = (used2 & 2u) ? LL_INF : m1;
            bool pickA = (ca <= cb2);
            long long mb = pickA ? ca : cb2;
            unsigned bj = pickA ? (unsigned)colA : (unsigned)colB;
            int psel    = pickA ? pr0 : pr1;

            // 52-bit key split: hi32 | (lo20, col6, p[col]6)
            unsigned hi, packv;
            if (mb >= BIAS51) { hi = 0xFFFFFFFFu; packv = 0xFFFFFFFFu; }
            else {
                unsigned long long key = (unsigned long long)(mb + BIAS51);
                hi = (unsigned)(key >> 20);
                packv = (((unsigned)key & 0xFFFFFu) << 12) | (bj << 6) | (unsigned)psel;
            }

            unsigned hmin = __reduce_min_sync(FULLMASK, hi);
            unsigned pk = (hi == hmin) ? packv : 0xFFFFFFFFu;
            unsigned pkm = __reduce_min_sync(FULLMASK, pk);
            unsigned jmin = (pkm >> 6) & 63u;
            int pval = (int)(pkm & 63u);
            long long delta = (long long)((((unsigned long long)hmin << 20) | (pkm >> 12)))
                              - BIAS51;

            // dual / minv updates (exact)
            if (act) {
                if (used2 & 1u) { v0 -= delta; u0r += delta; } else { m0 -= delta; }
                if (used2 & 2u) { v1 -= delta; u1r += delta; } else { m1 -= delta; }
            }
            uirow += delta;

            j0 = (int)jmin;
            if (pval == 0) break;             // reached a free column
            if (lane == (int)((jmin - 1) >> 1)) used2 |= 1u << ((jmin - 1) & 1u);
            i0 = pval;
            ui0 = u_s[pval];                  // phase-start value (u_s untouched in-phase)
        }

        // write back u
        if (act) {
            if (used2 & 1u) u_s[pr0] = u0r;
            if (used2 & 2u) u_s[pr1] = u1r;
        }
        if (lane == 0) u_s[i] = uirow;
        __syncwarp();

        // augment alternating path
        if (lane == 0) {
            int jc = j0;
            while (jc) {
                int jn = way_s[jc];
                p_s[jc] = (jn == 0) ? i : p_s[jn];
                jc = jn;
            }
        }
        __syncwarp();
        if (act) { pr0 = p_s[colA]; pr1 = p_s[colB]; }
        __syncwarp();
    }

    // Emit matches: queries ascending (48 of 50 columns assigned)
    if (lane == 0) {
        int base = b * NMATCH + g * NT;
        int k = 0;
        for (int j = 1; j <= LSA_M; j++) {
            int pj = p_s[j];
            if (pj) {
                pi_out[base + k] = (float)(g * GQ + j - 1);
                ti_out[base + k] = (float)(pj - 1);
                k++;
            }
        }
    }
}

// ---------------------------------------------------------------------------
extern "C" void kernel_launch(void* const* d_in, const int* in_sizes, int n_in,
                              void* d_out, int out_size)
{
    const float* logits = (const float*)d_in[0];  // (16,550,91)
    const float* pboxes = (const float*)d_in[1];  // (16,550,6)
    const int*   labels = (const int*)  d_in[2];  // (16,48)
    const float* tboxes = (const float*)d_in[3];  // (16,48,6)

    float* C  = (float*)d_out;
    const int C_ELEMS = BS * NQ * NTOT;          // 6,758,400
    float* pi = C + C_ELEMS;
    float* ti = pi + BS * NMATCH;

    int nfoc = BS * NQ * NC;
    focal_kernel<<<(nfoc + 255) / 256, 256>>>(logits);

    int do_lsa = (out_size >= C_ELEMS + 2 * BS * NMATCH) ? 1 : 0;
    fused_kernel<<<NPROB + COST_BLOCKS, 256>>>(pboxes, labels, tboxes,
                                               C, pi, ti, do_lsa);
}

// round 12
// speedup vs baseline: 6.8520x; 1.2630x over previous
#include <cuda_runtime.h>
#include <math.h>

// Problem constants (fixed by setup_inputs)
#define BS   16
#define NQ   550
#define NC   91
#define NT   48
#define GN   11
#define GQ   (NQ / GN)       // 50
#define NTOT (BS * NT)       // 768
#define NMATCH (GN * NT)     // 528

#define LSA_N 48   // rows (targets) of transposed problem
#define LSA_M 50   // cols (queries)
#define NPROB (BS * GN)      // 176 LSA problems
#define COST_BLOCKS 6600     // 6,758,400 / (256*4)
#define FULLMASK 0xffffffffu

#define SCALE39 549755813888.0      // 2^39 fixed-point scale
#define BIAS51  (1LL << 51)
#define LL_INF  0x7FFFFFFFFFFFFFFFLL

// ---------------------------------------------------------------------------
// focal class cost (inlined everywhere; identical f32 expression)
// ---------------------------------------------------------------------------
__device__ __forceinline__ float focal_eval(float x)
{
    float p = 1.0f / (1.0f + expf(-x));
    float omp = 1.0f - p;
    float pos = 0.25f * omp * omp * (-logf(p + 1e-8f));
    float neg = 0.75f * p * p * (-logf(omp + 1e-8f));
    return pos - neg;
}

// ---------------------------------------------------------------------------
// Shared cost evaluation (identical expression everywhere)
// ---------------------------------------------------------------------------
__device__ __forceinline__ float cost_eval(
    float cx, float cy, float l, float r, float tp, float bo,
    int q, int t,
    const float* __restrict__ logits,
    const int* __restrict__ labels, const float* __restrict__ tboxes)
{
    const float* tb = tboxes + t * 6;
    float tcx = tb[0], tcy = tb[1], tl = tb[2], tr = tb[3], ttp = tb[4], tbo = tb[5];

    float cost_class = focal_eval(logits[q * NC + labels[t]]);

    float c3d   = fabsf(cx - tcx) + fabsf(cy - tcy);
    float cbbox = fabsf(l - tl) + fabsf(r - tr) + fabsf(tp - ttp) + fabsf(bo - tbo);

    float ax0 = cx - l,   ay0 = cy - tp,   ax1 = cx + r,   ay1 = cy + bo;
    float bx0 = tcx - tl, by0 = tcy - ttp, bx1 = tcx + tr, by1 = tcy + tbo;
    float a1 = (ax1 - ax0) * (ay1 - ay0);
    float a2 = (bx1 - bx0) * (by1 - by0);
    float iw = fmaxf(fminf(ax1, bx1) - fmaxf(ax0, bx0), 0.0f);
    float ih = fmaxf(fminf(ay1, by1) - fmaxf(ay0, by0), 0.0f);
    float inter = iw * ih;
    float uni = a1 + a2 - inter;
    float iou = inter / uni;
    float ew = fmaxf(fmaxf(ax1, bx1) - fminf(ax0, bx0), 0.0f);
    float eh = fmaxf(fmaxf(ay1, by1) - fminf(ay0, by0), 0.0f);
    float ae = ew * eh;
    float giou = iou - (ae - uni) / ae;

    return 5.0f * cbbox + 10.0f * c3d + 2.0f * cost_class + 2.0f * (-giou);
}

// warp-min over 58-bit keys packed as ((val+BIAS51)<<6)|col ; ~0ULL = inactive
__device__ __forceinline__ unsigned long long warp_min58(unsigned long long key)
{
    unsigned hi = (unsigned)(key >> 32);
    unsigned hmin = __reduce_min_sync(FULLMASK, hi);
    unsigned lo = (hi == hmin) ? (unsigned)key : 0xFFFFFFFFu;
    unsigned lmin = __reduce_min_sync(FULLMASK, lo);
    return ((unsigned long long)hmin << 32) | lmin;
}

// ---------------------------------------------------------------------------
// Fused kernel: blocks [0, NPROB) run JV-LSA (s64 fixed-point, row-reduction
// + greedy + 2-pass ARR + frame-invariant shortest-path phases),
// blocks [NPROB, ...) fill the full cost matrix C. Concurrent in one launch.
// ---------------------------------------------------------------------------
__global__ void __launch_bounds__(256)
fused_kernel(const float* __restrict__ logits,
             const float* __restrict__ pboxes,
             const int*   __restrict__ labels,
             const float* __restrict__ tboxes,
             float* __restrict__ C,
             float* __restrict__ pi_out,
             float* __restrict__ ti_out,
             int do_lsa)
{
    // ---------------- cost-matrix cohort ----------------
    if (blockIdx.x >= NPROB) {
        int cb = blockIdx.x - NPROB;
        int base = (cb * 256 + threadIdx.x) * 4;
        int q = base / NTOT;
        int t0 = base - q * NTOT;
        const float* qb = pboxes + q * 6;
        float cx = qb[0], cy = qb[1], l = qb[2], r = qb[3], tp = qb[4], bo = qb[5];
        float4 out;
        out.x = cost_eval(cx, cy, l, r, tp, bo, q, t0 + 0, logits, labels, tboxes);
        out.y = cost_eval(cx, cy, l, r, tp, bo, q, t0 + 1, logits, labels, tboxes);
        out.z = cost_eval(cx, cy, l, r, tp, bo, q, t0 + 2, logits, labels, tboxes);
        out.w = cost_eval(cx, cy, l, r, tp, bo, q, t0 + 3, logits, labels, tboxes);
        *(float4*)&C[base] = out;
        return;
    }

    // ---------------- LSA cohort ----------------
    if (!do_lsa) return;
    int prob = blockIdx.x;
    int b = prob / GN;
    int g = prob - b * GN;
    int tid = threadIdx.x;

    __shared__ long long costp[LSA_N][64];   // fixed-point costs, 2 cols/lane adjacent
    __shared__ long long u_s[LSA_N + 1];
    __shared__ int p_s[LSA_M + 1];
    __shared__ int way_s[LSA_M + 1];
    __shared__ int rowmin_j[LSA_N + 1];
    __shared__ int claim[LSA_M + 1];
    __shared__ int row_done[LSA_N + 1];

    // all 256 threads compute + quantize the 48x50 diagonal tile
    for (int idx = tid; idx < LSA_N * LSA_M; idx += 256) {
        int jj = idx / LSA_N;
        int i  = idx - jj * LSA_N;
        int q = b * NQ + g * GQ + jj;
        const float* qb = pboxes + q * 6;
        float c = cost_eval(qb[0], qb[1], qb[2], qb[3], qb[4], qb[5],
                            q, b * NT + i, logits, labels, tboxes);
        costp[i][jj] = __double2ll_rn((double)c * SCALE39);
    }
    if (tid >= 64 && tid < 64 + LSA_M + 1) {
        p_s[tid - 64] = 0; way_s[tid - 64] = 0; claim[tid - 64] = 1 << 30;
    }
    if (tid == 63) u_s[0] = 0LL;
    __syncthreads();

    // warm start: u[i] = row min (exact), greedy claim of argmin columns
    if (tid < LSA_N) {
        int i = tid;
        long long bestk = LL_INF;
        #pragma unroll 1
        for (int s = 0; s < LSA_M; s++) {
            int jj = i + s; if (jj >= LSA_M) jj -= LSA_M;   // staggered, conflict-free
            long long kk = ((costp[i][jj] + BIAS51) << 6) | jj;  // tie -> smaller j
            if (kk < bestk) bestk = kk;
        }
        int jarg = (int)(bestk & 63);
        u_s[i + 1] = (bestk >> 6) - BIAS51;
        rowmin_j[i + 1] = jarg + 1;
        row_done[i + 1] = 0;
        atomicMin(&claim[jarg + 1], i + 1);    // smallest row wins = row-order greedy
    }
    __syncthreads();
    if (tid < LSA_N) {
        int i = tid + 1;
        int j = rowmin_j[i];
        if (claim[j] == i) { p_s[j] = i; row_done[i] = 1; }  // tight edge
    }
    __syncthreads();
    if (tid >= 32) return;

    int lane = tid;
    const bool act = (lane < 25);
    const int colA = 2 * lane + 1;          // 1-based owned columns
    const int colB = 2 * lane + 2;
    long long v0 = 0, v1 = 0;

    // ------- augmenting row reduction: exactly 2 passes over free rows -------
    for (int pass = 0; pass < 2; pass++) {
        for (int i = 1; i <= LSA_N; i++) {
            if (row_done[i]) continue;

            longlong2 cf = *(const longlong2*)&costp[i - 1][2 * lane];
            unsigned long long kA = ~0ULL, kB = ~0ULL;
            if (act) {
                kA = ((unsigned long long)(cf.x - v0 + BIAS51) << 6) | (unsigned)colA;
                kB = ((unsigned long long)(cf.y - v1 + BIAS51) << 6) | (unsigned)colB;
            }
            unsigned long long kloc = (kA <= kB) ? kA : kB;
            unsigned long long k1 = warp_min58(kloc);
            int j1 = (int)(k1 & 63u);
            long long val1 = (long long)(k1 >> 6) - BIAS51;

            unsigned long long kA2 = (colA == j1) ? ~0ULL : kA;
            unsigned long long kB2 = (colB == j1) ? ~0ULL : kB;
            unsigned long long kloc2 = (kA2 <= kB2) ? kA2 : kB2;
            unsigned long long k2 = warp_min58(kloc2);
            int j2 = (int)(k2 & 63u);
            long long val2 = (long long)(k2 >> 6) - BIAS51;

            int jsel = j1;
            if (val1 == val2 && p_s[j1] != 0) jsel = j2;   // tie: try second column
            int kdisp = p_s[jsel];
            __syncwarp();
            if (lane == 0) {
                p_s[jsel] = i;
                u_s[i] = val2;
                row_done[i] = 1;
                if (kdisp) row_done[kdisp] = 0;   // displaced row becomes free
            }
            if (val1 < val2) {                     // lower v[j1] so it stays tight
                int owner = (j1 - 1) >> 1;
                if (lane == owner) {
                    if ((j1 - 1) & 1) v1 -= (val2 - val1); else v0 -= (val2 - val1);
                }
            }
            __syncwarp();
        }
    }

    int pr0 = 0, pr1 = 0;
    if (act) { pr0 = p_s[colA]; pr1 = p_s[colB]; }
    __syncwarp();

    // ------- frame-invariant successive shortest-path phases -------
    // M[j] = min_t (cur_t[j] + S_{t-1}); selection and way updates are
    // bit-identical to the reference recurrence (exact integer telescoping).
    for (int i = 1; i <= LSA_N; i++) {
        if (row_done[i]) continue;

        long long M0 = LL_INF, M1 = LL_INF;
        unsigned used2 = act ? 0u : 3u;
        long long S = 0;                    // S_{t-1}
        long long ui0 = u_s[i];             // phase-start u of scan row
        int i0 = i;
        int j0 = 0;

        while (true) {
            // relax free columns from row i0 (exact integer arithmetic)
            longlong2 cf = *(const longlong2*)&costp[i0 - 1][2 * lane];
            if (act) {
                long long base = S - ui0;
                if (!(used2 & 1u)) {
                    long long cur = cf.x - v0 + base;
                    if (cur < M0) { M0 = cur; way_s[colA] = j0; }
                }
                if (!(used2 & 2u)) {
                    long long cur = cf.y - v1 + base;
                    if (cur < M1) { M1 = cur; way_s[colB] = j0; }
                }
            }

            // lane-local best among not-used (tie -> colA, the smaller index)
            long long ca  = (used2 & 1u) ? LL_INF : M0;
            long long cb2 = (used2 & 2u) ? LL_INF : M1;
            bool pickA = (ca <= cb2);
            long long mb = pickA ? ca : cb2;
            unsigned bj = pickA ? (unsigned)colA : (unsigned)colB;
            int psel    = pickA ? pr0 : pr1;

            // 52-bit key split: hi32 | (lo20, col6, p[col]6)
            unsigned hi, packv;
            if (mb >= BIAS51) { hi = 0xFFFFFFFFu; packv = 0xFFFFFFFFu; }
            else {
                unsigned long long key = (unsigned long long)(mb + BIAS51);
                hi = (unsigned)(key >> 20);
                packv = (((unsigned)key & 0xFFFFFu) << 12) | (bj << 6) | (unsigned)psel;
            }

            unsigned hmin = __reduce_min_sync(FULLMASK, hi);
            unsigned pk = (hi == hmin) ? packv : 0xFFFFFFFFu;
            unsigned pkm = __reduce_min_sync(FULLMASK, pk);
            unsigned jmin = (pkm >> 6) & 63u;
            int pval = (int)(pkm & 63u);
            S = (long long)((((unsigned long long)hmin << 20) | (pkm >> 12))) - BIAS51;

            j0 = (int)jmin;
            if (pval == 0) break;             // reached a free column
            if (lane == (int)((jmin - 1) >> 1)) used2 |= 1u << ((jmin - 1) & 1u);
            i0 = pval;
            ui0 = u_s[pval];                  // phase-start value (u_s untouched in-phase)
        }

        // phase-end dual reconciliation: d_j = S_end - M[j] for used columns
        long long S_end = S;
        if (act) {
            if (used2 & 1u) { long long d = S_end - M0; v0 -= d; u_s[pr0] += d; }
            if (used2 & 2u) { long long d = S_end - M1; v1 -= d; u_s[pr1] += d; }
        }
        if (lane == 0) u_s[i] += S_end;
        __syncwarp();

        // augment alternating path
        if (lane == 0) {
            int jc = j0;
            while (jc) {
                int jn = way_s[jc];
                p_s[jc] = (jn == 0) ? i : p_s[jn];
                jc = jn;
            }
        }
        __syncwarp();
        if (act) { pr0 = p_s[colA]; pr1 = p_s[colB]; }
    }

    // Emit matches: queries ascending (48 of 50 columns assigned)
    if (lane == 0) {
        int base = b * NMATCH + g * NT;
        int k = 0;
        for (int j = 1; j <= LSA_M; j++) {
            int pj = p_s[j];
            if (pj) {
                pi_out[base + k] = (float)(g * GQ + j - 1);
                ti_out[base + k] = (float)(pj - 1);
                k++;
            }
        }
    }
}

// ---------------------------------------------------------------------------
extern "C" void kernel_launch(void* const* d_in, const int* in_sizes, int n_in,
                              void* d_out, int out_size)
{
    const float* logits = (const float*)d_in[0];  // (16,550,91)
    const float* pboxes = (const float*)d_in[1];  // (16,550,6)
    const int*   labels = (const int*)  d_in[2];  // (16,48)
    const float* tboxes = (const float*)d_in[3];  // (16,48,6)

    float* C  = (float*)d_out;
    const int C_ELEMS = BS * NQ * NTOT;          // 6,758,400
    float* pi = C + C_ELEMS;
    float* ti = pi + BS * NMATCH;

    int do_lsa = (out_size >= C_ELEMS + 2 * BS * NMATCH) ? 1 : 0;
    fused_kernel<<<NPROB + COST_BLOCKS, 256>>>(logits, pboxes, labels, tboxes,
                                               C, pi, ti, do_lsa);
}

// round 14
// speedup vs baseline: 7.6861x; 1.1217x over previous
#include <cuda_runtime.h>
#include <math.h>

// Problem constants (fixed by setup_inputs)
#define BS   16
#define NQ   550
#define NC   91
#define NT   48
#define GN   11
#define GQ   (NQ / GN)       // 50
#define NTOT (BS * NT)       // 768
#define NMATCH (GN * NT)     // 528

#define LSA_N 48   // rows (targets) of transposed problem
#define LSA_M 50   // cols (queries)
#define NPROB (BS * GN)      // 176 LSA problems
#define NQROWS (BS * NQ)     // 8800 cost-matrix rows (one block each)
#define FULLMASK 0xffffffffu

#define SCALE39 549755813888.0      // 2^39 fixed-point scale
#define BIAS51  (1LL << 51)
#define LL_INF  0x7FFFFFFFFFFFFFFFLL

// ---------------------------------------------------------------------------
// focal class cost (identical f32 expression)
// ---------------------------------------------------------------------------
__device__ __forceinline__ float focal_eval(float x)
{
    float p = 1.0f / (1.0f + expf(-x));
    float omp = 1.0f - p;
    float pos = 0.25f * omp * omp * (-logf(p + 1e-8f));
    float neg = 0.75f * p * p * (-logf(omp + 1e-8f));
    return pos - neg;
}

// ---------------------------------------------------------------------------
// box/giou part of the cost, given precomputed query-box quantities and a
// target's raw box. Identical float expression/order to the reference path.
// ---------------------------------------------------------------------------
__device__ __forceinline__ float cost_box(
    float cx, float cy, float l, float r, float tp, float bo,
    float ax0, float ay0, float ax1, float ay1, float a1,
    const float* __restrict__ tb, float cost_class)
{
    float tcx = tb[0], tcy = tb[1], tl = tb[2], tr = tb[3], ttp = tb[4], tbo = tb[5];

    float c3d   = fabsf(cx - tcx) + fabsf(cy - tcy);
    float cbbox = fabsf(l - tl) + fabsf(r - tr) + fabsf(tp - ttp) + fabsf(bo - tbo);

    float bx0 = tcx - tl, by0 = tcy - ttp, bx1 = tcx + tr, by1 = tcy + tbo;
    float a2 = (bx1 - bx0) * (by1 - by0);
    float iw = fmaxf(fminf(ax1, bx1) - fmaxf(ax0, bx0), 0.0f);
    float ih = fmaxf(fminf(ay1, by1) - fmaxf(ay0, by0), 0.0f);
    float inter = iw * ih;
    float uni = a1 + a2 - inter;
    float iou = inter / uni;
    float ew = fmaxf(fmaxf(ax1, bx1) - fminf(ax0, bx0), 0.0f);
    float eh = fmaxf(fmaxf(ay1, by1) - fminf(ay0, by0), 0.0f);
    float ae = ew * eh;
    float giou = iou - (ae - uni) / ae;

    return 5.0f * cbbox + 10.0f * c3d + 2.0f * cost_class + 2.0f * (-giou);
}

// full cost for LSA tile path (computes focal inline; same expression)
__device__ __forceinline__ float cost_eval(
    float cx, float cy, float l, float r, float tp, float bo,
    int q, int t,
    const float* __restrict__ logits,
    const int* __restrict__ labels, const float* __restrict__ tboxes)
{
    float ax0 = cx - l, ay0 = cy - tp, ax1 = cx + r, ay1 = cy + bo;
    float a1 = (ax1 - ax0) * (ay1 - ay0);
    float cc = focal_eval(logits[q * NC + labels[t]]);
    return cost_box(cx, cy, l, r, tp, bo, ax0, ay0, ax1, ay1, a1,
                    tboxes + t * 6, cc);
}

// warp-min over 58-bit keys packed as ((val+BIAS51)<<6)|col ; ~0ULL = inactive
__device__ __forceinline__ unsigned long long warp_min58(unsigned long long key)
{
    unsigned hi = (unsigned)(key >> 32);
    unsigned hmin = __reduce_min_sync(FULLMASK, hi);
    unsigned lo = (hi == hmin) ? (unsigned)key : 0xFFFFFFFFu;
    unsigned lmin = __reduce_min_sync(FULLMASK, lo);
    return ((unsigned long long)hmin << 32) | lmin;
}

// ---------------------------------------------------------------------------
// Fused kernel: blocks [0, NPROB) run JV-LSA; blocks [NPROB, NPROB+NQROWS)
// each fill ONE row of C with a per-block smem focal table (class dedup).
// ---------------------------------------------------------------------------
__global__ void __launch_bounds__(256)
fused_kernel(const float* __restrict__ logits,
             const float* __restrict__ pboxes,
             const int*   __restrict__ labels,
             const float* __restrict__ tboxes,
             float* __restrict__ C,
             float* __restrict__ pi_out,
             float* __restrict__ ti_out,
             int do_lsa)
{
    int tid = threadIdx.x;

    // ---------------- cost-matrix cohort: one q row per block ----------------
    if (blockIdx.x >= NPROB) {
        int q = blockIdx.x - NPROB;          // 0..NQROWS-1
        __shared__ float foc[NC];
        if (tid < NC) foc[tid] = focal_eval(logits[q * NC + tid]);
        __syncthreads();

        const float* qb = pboxes + q * 6;
        float cx = qb[0], cy = qb[1], l = qb[2], r = qb[3], tp = qb[4], bo = qb[5];
        float ax0 = cx - l, ay0 = cy - tp, ax1 = cx + r, ay1 = cy + bo;
        float a1 = (ax1 - ax0) * (ay1 - ay0);

        #pragma unroll
        for (int k = 0; k < NTOT / 256; k++) {
            int t = tid + k * 256;
            float cc = foc[labels[t]];
            C[q * NTOT + t] = cost_box(cx, cy, l, r, tp, bo,
                                       ax0, ay0, ax1, ay1, a1,
                                       tboxes + t * 6, cc);
        }
        return;
    }

    // ---------------- LSA cohort ----------------
    if (!do_lsa) return;
    int prob = blockIdx.x;
    int b = prob / GN;
    int g = prob - b * GN;

    __shared__ long long costp[LSA_N][64];   // fixed-point costs, 2 cols/lane adjacent
    __shared__ long long u_s[LSA_N + 1];
    __shared__ int p_s[LSA_M + 1];
    __shared__ int way_s[LSA_M + 1];
    __shared__ int rowmin_j[LSA_N + 1];
    __shared__ int claim[LSA_M + 1];
    __shared__ int row_done[LSA_N + 1];

    // all 256 threads compute + quantize the 48x50 diagonal tile
    for (int idx = tid; idx < LSA_N * LSA_M; idx += 256) {
        int jj = idx / LSA_N;
        int i  = idx - jj * LSA_N;
        int q = b * NQ + g * GQ + jj;
        const float* qb = pboxes + q * 6;
        float c = cost_eval(qb[0], qb[1], qb[2], qb[3], qb[4], qb[5],
                            q, b * NT + i, logits, labels, tboxes);
        costp[i][jj] = __double2ll_rn((double)c * SCALE39);
    }
    if (tid >= 64 && tid < 64 + LSA_M + 1) {
        p_s[tid - 64] = 0; way_s[tid - 64] = 0; claim[tid - 64] = 1 << 30;
    }
    if (tid == 63) u_s[0] = 0LL;
    __syncthreads();

    // warm start: u[i] = row min (exact), greedy claim of argmin columns
    if (tid < LSA_N) {
        int i = tid;
        long long bestk = LL_INF;
        #pragma unroll 1
        for (int s = 0; s < LSA_M; s++) {
            int jj = i + s; if (jj >= LSA_M) jj -= LSA_M;   // staggered, conflict-free
            long long kk = ((costp[i][jj] + BIAS51) << 6) | jj;  // tie -> smaller j
            if (kk < bestk) bestk = kk;
        }
        int jarg = (int)(bestk & 63);
        u_s[i + 1] = (bestk >> 6) - BIAS51;
        rowmin_j[i + 1] = jarg + 1;
        row_done[i + 1] = 0;
        atomicMin(&claim[jarg + 1], i + 1);    // smallest row wins = row-order greedy
    }
    __syncthreads();
    if (tid < LSA_N) {
        int i = tid + 1;
        int j = rowmin_j[i];
        if (claim[j] == i) { p_s[j] = i; row_done[i] = 1; }  // tight edge
    }
    __syncthreads();
    if (tid >= 32) return;

    int lane = tid;
    const bool act = (lane < 25);
    const int colA = 2 * lane + 1;          // 1-based owned columns
    const int colB = 2 * lane + 2;
    long long v0 = 0, v1 = 0;

    // ------- augmenting row reduction: 3 passes over free rows -------
    for (int pass = 0; pass < 3; pass++) {
        for (int i = 1; i <= LSA_N; i++) {
            if (row_done[i]) continue;

            longlong2 cf = *(const longlong2*)&costp[i - 1][2 * lane];
            unsigned long long kA = ~0ULL, kB = ~0ULL;
            if (act) {
                kA = ((unsigned long long)(cf.x - v0 + BIAS51) << 6) | (unsigned)colA;
                kB = ((unsigned long long)(cf.y - v1 + BIAS51) << 6) | (unsigned)colB;
            }
            unsigned long long kloc = (kA <= kB) ? kA : kB;
            unsigned long long k1 = warp_min58(kloc);
            int j1 = (int)(k1 & 63u);
            long long val1 = (long long)(k1 >> 6) - BIAS51;

            unsigned long long kA2 = (colA == j1) ? ~0ULL : kA;
            unsigned long long kB2 = (colB == j1) ? ~0ULL : kB;
            unsigned long long kloc2 = (kA2 <= kB2) ? kA2 : kB2;
            unsigned long long k2 = warp_min58(kloc2);
            int j2 = (int)(k2 & 63u);
            long long val2 = (long long)(k2 >> 6) - BIAS51;

            int jsel = j1;
            if (val1 == val2 && p_s[j1] != 0) jsel = j2;   // tie: try second column
            int kdisp = p_s[jsel];
            __syncwarp();
            if (lane == 0) {
                p_s[jsel] = i;
                u_s[i] = val2;
                row_done[i] = 1;
                if (kdisp) row_done[kdisp] = 0;   // displaced row becomes free
            }
            if (val1 < val2) {                     // lower v[j1] so it stays tight
                int owner = (j1 - 1) >> 1;
                if (lane == owner) {
                    if ((j1 - 1) & 1) v1 -= (val2 - val1); else v0 -= (val2 - val1);
                }
            }
            __syncwarp();
        }
    }

    int pr0 = 0, pr1 = 0;
    if (act) { pr0 = p_s[colA]; pr1 = p_s[colB]; }
    __syncwarp();

    // ------- frame-invariant successive shortest-path phases -------
    // M[j] = min_t (cur_t[j] + S_{t-1}); selection/way updates bit-identical
    // to the reference recurrence (exact integer telescoping).
    for (int i = 1; i <= LSA_N; i++) {
        if (row_done[i]) continue;

        long long M0 = LL_INF, M1 = LL_INF;
        unsigned used2 = act ? 0u : 3u;
        long long S = 0;                    // S_{t-1}
        long long ui0 = u_s[i];             // phase-start u of scan row
        int i0 = i;
        int j0 = 0;

        while (true) {
            // relax free columns from row i0 (exact integer arithmetic)
            longlong2 cf = *(const longlong2*)&costp[i0 - 1][2 * lane];
            if (act) {
                long long base = S - ui0;
                if (!(used2 & 1u)) {
                    long long cur = cf.x - v0 + base;
                    if (cur < M0) { M0 = cur; way_s[colA] = j0; }
                }
                if (!(used2 & 2u)) {
                    long long cur = cf.y - v1 + base;
                    if (cur < M1) { M1 = cur; way_s[colB] = j0; }
                }
            }

            // lane-local best among not-used (tie -> colA, the smaller index)
            long long ca  = (used2 & 1u) ? LL_INF : M0;
            long long cb2 = (used2 & 2u) ? LL_INF : M1;
            bool pickA = (ca <= cb2);
            long long mb = pickA ? ca : cb2;
            unsigned bj = pickA ? (unsigned)colA : (unsigned)colB;
            int psel    = pickA ? pr0 : pr1;

            // 52-bit key split: hi32 | (lo20, col6, p[col]6)
            unsigned hi, packv;
            if (mb >= BIAS51) { hi = 0xFFFFFFFFu; packv = 0xFFFFFFFFu; }
            else {
                unsigned long long key = (unsigned long long)(mb + BIAS51);
                hi = (unsigned)(key >> 20);
                packv = (((unsigned)key & 0xFFFFFu) << 12) | (bj << 6) | (unsigned)psel;
            }

            unsigned hmin = __reduce_min_sync(FULLMASK, hi);
            unsigned pk = (hi == hmin) ? packv : 0xFFFFFFFFu;
            unsigned pkm = __reduce_min_sync(FULLMASK, pk);
            unsigned jmin = (pkm >> 6) & 63u;
            int pval = (int)(pkm & 63u);
            S = (long long)((((unsigned long long)hmin << 20) | (pkm >> 12))) - BIAS51;

            j0 = (int)jmin;
            if (pval == 0) break;             // reached a free column
            if (lane == (int)((jmin - 1) >> 1)) used2 |= 1u << ((jmin - 1) & 1u);
            i0 = pval;
            ui0 = u_s[pval];                  // phase-start value (u_s untouched in-phase)
        }

        // phase-end dual reconciliation: d_j = S_end - M[j] for used columns
        long long S_end = S;
        if (act) {
            if (used2 & 1u) { long long d = S_end - M0; v0 -= d; u_s[pr0] += d; }
            if (used2 & 2u) { long long d = S_end - M1; v1 -= d; u_s[pr1] += d; }
        }
        if (lane == 0) u_s[i] += S_end;
        __syncwarp();

        // augment alternating path
        if (lane == 0) {
            int jc = j0;
            while (jc) {
                int jn = way_s[jc];
                p_s[jc] = (jn == 0) ? i : p_s[jn];
                jc = jn;
            }
        }
        __syncwarp();
        if (act) { pr0 = p_s[colA]; pr1 = p_s[colB]; }
    }

    // Emit matches: queries ascending (48 of 50 columns assigned)
    if (lane == 0) {
        int base = b * NMATCH + g * NT;
        int k = 0;
        for (int j = 1; j <= LSA_M; j++) {
            int pj = p_s[j];
            if (pj) {
                pi_out[base + k] = (float)(g * GQ + j - 1);
                ti_out[base + k] = (float)(pj - 1);
                k++;
            }
        }
    }
}

// ---------------------------------------------------------------------------
extern "C" void kernel_launch(void* const* d_in, const int* in_sizes, int n_in,
                              void* d_out, int out_size)
{
    const float* logits = (const float*)d_in[0];  // (16,550,91)
    const float* pboxes = (const float*)d_in[1];  // (16,550,6)
    const int*   labels = (const int*)  d_in[2];  // (16,48)
    const float* tboxes = (const float*)d_in[3];  // (16,48,6)

    float* C  = (float*)d_out;
    const int C_ELEMS = BS * NQ * NTOT;          // 6,758,400
    float* pi = C + C_ELEMS;
    float* ti = pi + BS * NMATCH;

    int do_lsa = (out_size >= C_ELEMS + 2 * BS * NMATCH) ? 1 : 0;
    fused_kernel<<<NPROB + NQROWS, 256>>>(logits, pboxes, labels, tboxes,
                                          C, pi, ti, do_lsa);
}

// round 15
// speedup vs baseline: 10.0151x; 1.3030x over previous
#include <cuda_runtime.h>
#include <math.h>

// Problem constants (fixed by setup_inputs)
#define BS   16
#define NQ   550
#define NC   91
#define NT   48
#define GN   11
#define GQ   (NQ / GN)       // 50
#define NTOT (BS * NT)       // 768
#define NMATCH (GN * NT)     // 528

#define LSA_N 48   // rows (targets) of transposed problem
#define LSA_M 50   // cols (queries)
#define NPROB (BS * GN)      // 176 LSA problems
#define NQROWS (BS * NQ)     // 8800 cost-matrix rows (one block each)
#define FULLMASK 0xffffffffu
#define ARR_PASSES 4

#define SCALE39 549755813888.0      // 2^39 fixed-point scale
#define BIAS51  (1LL << 51)
#define PADV    (1LL << 50)         // sentinel: scaled "2048", >> any real cost
#define USEDV   ((1LL << 51) - 1)   // used-column candidate sentinel
#define LL_INF  0x7FFFFFFFFFFFFFFFLL

// ---------------------------------------------------------------------------
// focal class cost (identical f32 expression)
// ---------------------------------------------------------------------------
__device__ __forceinline__ float focal_eval(float x)
{
    float p = 1.0f / (1.0f + expf(-x));
    float omp = 1.0f - p;
    float pos = 0.25f * omp * omp * (-logf(p + 1e-8f));
    float neg = 0.75f * p * p * (-logf(omp + 1e-8f));
    return pos - neg;
}

// ---------------------------------------------------------------------------
// box/giou part of the cost (identical float expression/order everywhere)
// ---------------------------------------------------------------------------
__device__ __forceinline__ float cost_box(
    float cx, float cy, float l, float r, float tp, float bo,
    float ax0, float ay0, float ax1, float ay1, float a1,
    const float* __restrict__ tb, float cost_class)
{
    float tcx = tb[0], tcy = tb[1], tl = tb[2], tr = tb[3], ttp = tb[4], tbo = tb[5];

    float c3d   = fabsf(cx - tcx) + fabsf(cy - tcy);
    float cbbox = fabsf(l - tl) + fabsf(r - tr) + fabsf(tp - ttp) + fabsf(bo - tbo);

    float bx0 = tcx - tl, by0 = tcy - ttp, bx1 = tcx + tr, by1 = tcy + tbo;
    float a2 = (bx1 - bx0) * (by1 - by0);
    float iw = fmaxf(fminf(ax1, bx1) - fmaxf(ax0, bx0), 0.0f);
    float ih = fmaxf(fminf(ay1, by1) - fmaxf(ay0, by0), 0.0f);
    float inter = iw * ih;
    float uni = a1 + a2 - inter;
    float iou = inter / uni;
    float ew = fmaxf(fmaxf(ax1, bx1) - fminf(ax0, bx0), 0.0f);
    float eh = fmaxf(fmaxf(ay1, by1) - fminf(ay0, by0), 0.0f);
    float ae = ew * eh;
    float giou = iou - (ae - uni) / ae;

    return 5.0f * cbbox + 10.0f * c3d + 2.0f * cost_class + 2.0f * (-giou);
}

// full cost for LSA tile path (computes focal inline; same expression)
__device__ __forceinline__ float cost_eval(
    float cx, float cy, float l, float r, float tp, float bo,
    int q, int t,
    const float* __restrict__ logits,
    const int* __restrict__ labels, const float* __restrict__ tboxes)
{
    float ax0 = cx - l, ay0 = cy - tp, ax1 = cx + r, ay1 = cy + bo;
    float a1 = (ax1 - ax0) * (ay1 - ay0);
    float cc = focal_eval(logits[q * NC + labels[t]]);
    return cost_box(cx, cy, l, r, tp, bo, ax0, ay0, ax1, ay1, a1,
                    tboxes + t * 6, cc);
}

// warp-min over 58-bit keys packed as ((val+BIAS51)<<6)|col
__device__ __forceinline__ unsigned long long warp_min58(unsigned long long key)
{
    unsigned hi = (unsigned)(key >> 32);
    unsigned hmin = __reduce_min_sync(FULLMASK, hi);
    unsigned lo = (hi == hmin) ? (unsigned)key : 0xFFFFFFFFu;
    unsigned lmin = __reduce_min_sync(FULLMASK, lo);
    return ((unsigned long long)hmin << 32) | lmin;
}

// ---------------------------------------------------------------------------
// Fused kernel: blocks [0, NPROB) run JV-LSA; blocks [NPROB, NPROB+NQROWS)
// each fill ONE row of C with a per-block smem focal table (class dedup).
// ---------------------------------------------------------------------------
__global__ void __launch_bounds__(256)
fused_kernel(const float* __restrict__ logits,
             const float* __restrict__ pboxes,
             const int*   __restrict__ labels,
             const float* __restrict__ tboxes,
             float* __restrict__ C,
             float* __restrict__ pi_out,
             float* __restrict__ ti_out,
             int do_lsa)
{
    int tid = threadIdx.x;

    // ---------------- cost-matrix cohort: one q row per block ----------------
    if (blockIdx.x >= NPROB) {
        int q = blockIdx.x - NPROB;          // 0..NQROWS-1
        __shared__ float foc[NC];
        if (tid < NC) foc[tid] = focal_eval(logits[q * NC + tid]);
        __syncthreads();

        const float* qb = pboxes + q * 6;
        float cx = qb[0], cy = qb[1], l = qb[2], r = qb[3], tp = qb[4], bo = qb[5];
        float ax0 = cx - l, ay0 = cy - tp, ax1 = cx + r, ay1 = cy + bo;
        float a1 = (ax1 - ax0) * (ay1 - ay0);

        #pragma unroll
        for (int k = 0; k < NTOT / 256; k++) {
            int t = tid + k * 256;
            float cc = foc[labels[t]];
            C[q * NTOT + t] = cost_box(cx, cy, l, r, tp, bo,
                                       ax0, ay0, ax1, ay1, a1,
                                       tboxes + t * 6, cc);
        }
        return;
    }

    // ---------------- LSA cohort ----------------
    if (!do_lsa) return;
    int prob = blockIdx.x;
    int b = prob / GN;
    int g = prob - b * GN;

    __shared__ long long costp[LSA_N][64];   // fixed-point costs; cols 50..63 = PADV
    __shared__ long long u_s[LSA_N + 1];
    __shared__ int p_s[66];
    __shared__ int way_s[66];
    __shared__ int rowmin_j[LSA_N + 1];
    __shared__ int claim[LSA_M + 1];
    __shared__ int row_done[LSA_N + 1];

    // compute + quantize the 48x50 diagonal tile
    for (int idx = tid; idx < LSA_N * LSA_M; idx += 256) {
        int jj = idx / LSA_N;
        int i  = idx - jj * LSA_N;
        int q = b * NQ + g * GQ + jj;
        const float* qb = pboxes + q * 6;
        float c = cost_eval(qb[0], qb[1], qb[2], qb[3], qb[4], qb[5],
                            q, b * NT + i, logits, labels, tboxes);
        costp[i][jj] = __double2ll_rn((double)c * SCALE39);
    }
    // sentinel padding columns 50..63
    for (int idx = tid; idx < LSA_N * 14; idx += 256) {
        int i = idx / 14, c = 50 + (idx - (idx / 14) * 14);
        costp[i][c] = PADV;
    }
    if (tid >= 64 && tid < 64 + 66) { p_s[tid - 64] = 0; way_s[tid - 64] = 0; }
    if (tid >= 130 && tid < 130 + LSA_M + 1) claim[tid - 130] = 1 << 30;
    if (tid == 63) u_s[0] = 0LL;
    __syncthreads();

    // warm start: u[i] = row min (exact), greedy claim of argmin columns
    if (tid < LSA_N) {
        int i = tid;
        long long bestk = LL_INF;
        #pragma unroll 1
        for (int s = 0; s < LSA_M; s++) {
            int jj = i + s; if (jj >= LSA_M) jj -= LSA_M;   // staggered, conflict-free
            long long kk = ((costp[i][jj] + BIAS51) << 6) | jj;  // tie -> smaller j
            if (kk < bestk) bestk = kk;
        }
        int jarg = (int)(bestk & 63);
        u_s[i + 1] = (bestk >> 6) - BIAS51;
        rowmin_j[i + 1] = jarg + 1;
        row_done[i + 1] = 0;
        atomicMin(&claim[jarg + 1], i + 1);    // smallest row wins = row-order greedy
    }
    __syncthreads();
    if (tid < LSA_N) {
        int i = tid + 1;
        int j = rowmin_j[i];
        if (claim[j] == i) { p_s[j] = i; row_done[i] = 1; }  // tight edge
    }
    __syncthreads();
    if (tid >= 32) return;

    int lane = tid;
    const int colA = 2 * lane + 1;          // 1-based owned columns (pads >= 51)
    const int colB = 2 * lane + 2;
    long long v0 = 0, v1 = 0;

    // ------- augmenting row reduction over free rows (pad lanes never win) ---
    for (int pass = 0; pass < ARR_PASSES; pass++) {
        for (int i = 1; i <= LSA_N; i++) {
            if (row_done[i]) continue;

            longlong2 cf = *(const longlong2*)&costp[i - 1][2 * lane];
            unsigned long long kA =
                ((unsigned long long)(cf.x - v0 + BIAS51) << 6) | (unsigned)colA;
            unsigned long long kB =
                ((unsigned long long)(cf.y - v1 + BIAS51) << 6) | (unsigned)colB;
            unsigned long long kloc = (kA <= kB) ? kA : kB;
            unsigned long long k1 = warp_min58(kloc);
            int j1 = (int)(k1 & 63u);
            long long val1 = (long long)(k1 >> 6) - BIAS51;

            unsigned long long kA2 = (colA == j1) ? ~0ULL : kA;
            unsigned long long kB2 = (colB == j1) ? ~0ULL : kB;
            unsigned long long kloc2 = (kA2 <= kB2) ? kA2 : kB2;
            unsigned long long k2 = warp_min58(kloc2);
            int j2 = (int)(k2 & 63u);
            long long val2 = (long long)(k2 >> 6) - BIAS51;

            int jsel = j1;
            if (val1 == val2 && p_s[j1] != 0) jsel = j2;   // tie: try second column
            int kdisp = p_s[jsel];
            __syncwarp();
            if (lane == 0) {
                p_s[jsel] = i;
                u_s[i] = val2;
                row_done[i] = 1;
                if (kdisp) row_done[kdisp] = 0;   // displaced row becomes free
            }
            if (val1 < val2) {                     // lower v[j1] so it stays tight
                int owner = (j1 - 1) >> 1;
                if (lane == owner) {
                    if ((j1 - 1) & 1) v1 -= (val2 - val1); else v0 -= (val2 - val1);
                }
            }
            __syncwarp();
        }
    }

    int pr0 = p_s[colA];
    int pr1 = p_s[colB];
    __syncwarp();

    // ------- frame-invariant successive shortest-path phases -------
    // M[j] = min_t (cur_t[j] + S_{t-1}); exact integer telescoping of the
    // reference recurrence. Pad columns carry PADV and can never win.
    for (int i = 1; i <= LSA_N; i++) {
        if (row_done[i]) continue;

        long long M0 = PADV, M1 = PADV;
        unsigned used2 = 0;
        long long S = 0;                    // S_{t-1}
        long long ui0 = u_s[i];             // phase-start u of scan row
        int i0 = i;
        int j0 = 0;

        while (true) {
            // relax columns from row i0 (exact integer arithmetic, branch-free)
            longlong2 cf = *(const longlong2*)&costp[i0 - 1][2 * lane];
            long long base = S - ui0;
            long long cur0 = cf.x - v0 + base;
            if (cur0 < M0) { M0 = cur0; way_s[colA] = j0; }
            long long cur1 = cf.y - v1 + base;
            if (cur1 < M1) { M1 = cur1; way_s[colB] = j0; }

            // lane-local best among not-used (tie -> colA, the smaller index)
            long long ca  = (used2 & 1u) ? USEDV : M0;
            long long cb2 = (used2 & 2u) ? USEDV : M1;
            bool pickA = (ca <= cb2);
            long long mb = pickA ? ca : cb2;
            unsigned bj = pickA ? (unsigned)colA : (unsigned)colB;
            int psel    = pickA ? pr0 : pr1;

            // 52-bit key (unconditional): hi32 | (lo20, col6, p[col]6)
            unsigned long long key = (unsigned long long)(mb + BIAS51);
            unsigned hi = (unsigned)(key >> 20);
            unsigned packv = (((unsigned)key & 0xFFFFFu) << 12) | (bj << 6)
                             | (unsigned)psel;

            unsigned hmin = __reduce_min_sync(FULLMASK, hi);
            unsigned pk = (hi == hmin) ? packv : 0xFFFFFFFFu;
            unsigned pkm = __reduce_min_sync(FULLMASK, pk);
            unsigned jmin = (pkm >> 6) & 63u;
            int pval = (int)(pkm & 63u);
            S = (long long)((((unsigned long long)hmin << 20) | (pkm >> 12))) - BIAS51;

            j0 = (int)jmin;
            if (pval == 0) break;             // reached a free column
            if (lane == (int)((jmin - 1) >> 1)) used2 |= 1u << ((jmin - 1) & 1u);
            i0 = pval;
            ui0 = u_s[pval];                  // phase-start value (u_s untouched in-phase)
        }

        // phase-end dual reconciliation: d_j = S_end - M[j] for used columns
        long long S_end = S;
        if (used2 & 1u) { long long d = S_end - M0; v0 -= d; u_s[pr0] += d; }
        if (used2 & 2u) { long long d = S_end - M1; v1 -= d; u_s[pr1] += d; }
        if (lane == 0) u_s[i] += S_end;
        __syncwarp();

        // augment alternating path
        if (lane == 0) {
            int jc = j0;
            while (jc) {
                int jn = way_s[jc];
                p_s[jc] = (jn == 0) ? i : p_s[jn];
                jc = jn;
            }
        }
        __syncwarp();
        pr0 = p_s[colA];
        pr1 = p_s[colB];
    }

    // Emit matches: queries ascending (48 of 50 columns assigned)
    if (lane == 0) {
        int base = b * NMATCH + g * NT;
        int k = 0;
        for (int j = 1; j <= LSA_M; j++) {
            int pj = p_s[j];
            if (pj) {
                pi_out[base + k] = (float)(g * GQ + j - 1);
                ti_out[base + k] = (float)(pj - 1);
                k++;
            }
        }
    }
}

// ---------------------------------------------------------------------------
extern "C" void kernel_launch(void* const* d_in, const int* in_sizes, int n_in,
                              void* d_out, int out_size)
{
    const float* logits = (const float*)d_in[0];  // (16,550,91)
    const float* pboxes = (const float*)d_in[1];  // (16,550,6)
    const int*   labels = (const int*)  d_in[2];  // (16,48)
    const float* tboxes = (const float*)d_in[3];  // (16,48,6)

    float* C  = (float*)d_out;
    const int C_ELEMS = BS * NQ * NTOT;          // 6,758,400
    float* pi = C + C_ELEMS;
    float* ti = pi + BS * NMATCH;

    int do_lsa = (out_size >= C_ELEMS + 2 * BS * NMATCH) ? 1 : 0;
    fused_kernel<<<NPROB + NQROWS, 256>>>(logits, pboxes, labels, tboxes,
                                          C, pi, ti, do_lsa);
}